// round 1
// baseline (speedup 1.0000x reference)
#include <cuda_runtime.h>
#include <math.h>

// Problem constants
#define Bz   8
#define Cc   512
#define CQq  64
#define LL   96           // H == W == 96
#define HW   9216         // 96*96
#define BCHW 37748736     // 8*512*9216
#define BQHW 4718592      // 8*64*9216
#define ELN  7077888      // 8*96*96*96

// ---------------- scratch (device globals; allocation-free rule) ------------
__device__ float g_q [2][BQHW];   // [0]=qx [1]=qy   layout [B][CQ][H][W]
__device__ float g_k [2][BQHW];
__device__ float g_qT[2][BQHW];   // layout [B][CQ][W][H]
__device__ float g_kT[2][BQHW];
__device__ float g_v [2][BCHW];   // [B][C][H][W]
__device__ float g_vT[2][BCHW];   // [B][C][W][H]
__device__ float g_eH[2][ELN];    // energies->att  [B][W][H][Hk]  (dir0: q from x)
__device__ float g_eW[2][ELN];    // [B][H][W][Wk]
__device__ float g_tH[2][BCHW];   // applyH out  [B][W][C][H]   (index = output o)
__device__ float g_tW[2][BCHW];   // applyW out  [B][H][C][W]

// ---------------- 1x1 conv as GEMM: out[b,o,p] = sum_c W[o,c] x[b,c,p] + bias[o]
// grid: (HW/64, Cout/64, B), block 256, 4x4 register tile
__global__ void proj_kernel(const float* __restrict__ in, const float* __restrict__ Wm,
                            const float* __restrict__ bias, float* __restrict__ out,
                            int Cout)
{
    __shared__ float As[64][17];   // [m][k]
    __shared__ float Bs[16][64];   // [k][n]
    int b  = blockIdx.z;
    int bm = blockIdx.y * 64;
    int bn = blockIdx.x * 64;
    int t  = threadIdx.x;
    int tx = t & 15, ty = t >> 4;

    const float* inb = in + (size_t)b * Cc * HW;
    float acc[4][4];
#pragma unroll
    for (int i = 0; i < 4; i++)
#pragma unroll
        for (int j = 0; j < 4; j++) acc[i][j] = 0.f;

    for (int k0 = 0; k0 < Cc; k0 += 16) {
        // load A tile 64x16 (weights), float4 per thread
        {
            int m  = t >> 2;
            int kk = (t & 3) * 4;
            float4 w4 = *(const float4*)&Wm[(size_t)(bm + m) * Cc + k0 + kk];
            As[m][kk + 0] = w4.x; As[m][kk + 1] = w4.y;
            As[m][kk + 2] = w4.z; As[m][kk + 3] = w4.w;
        }
        // load B tile 16x64 (activations), coalesced
#pragma unroll
        for (int r = 0; r < 4; r++) {
            int idx = t + r * 256;
            int kk = idx >> 6, n = idx & 63;
            Bs[kk][n] = inb[(size_t)(k0 + kk) * HW + bn + n];
        }
        __syncthreads();
#pragma unroll
        for (int kk = 0; kk < 16; kk++) {
            float a0 = As[ty * 4 + 0][kk];
            float a1 = As[ty * 4 + 1][kk];
            float a2 = As[ty * 4 + 2][kk];
            float a3 = As[ty * 4 + 3][kk];
            float4 b4 = *(const float4*)&Bs[kk][tx * 4];
            acc[0][0] += a0 * b4.x; acc[0][1] += a0 * b4.y; acc[0][2] += a0 * b4.z; acc[0][3] += a0 * b4.w;
            acc[1][0] += a1 * b4.x; acc[1][1] += a1 * b4.y; acc[1][2] += a1 * b4.z; acc[1][3] += a1 * b4.w;
            acc[2][0] += a2 * b4.x; acc[2][1] += a2 * b4.y; acc[2][2] += a2 * b4.z; acc[2][3] += a2 * b4.w;
            acc[3][0] += a3 * b4.x; acc[3][1] += a3 * b4.y; acc[3][2] += a3 * b4.z; acc[3][3] += a3 * b4.w;
        }
        __syncthreads();
    }
#pragma unroll
    for (int i = 0; i < 4; i++) {
        int m = bm + ty * 4 + i;
        float bi = bias[m];
        float4 o4 = make_float4(acc[i][0] + bi, acc[i][1] + bi, acc[i][2] + bi, acc[i][3] + bi);
        *(float4*)&out[(size_t)b * Cout * HW + (size_t)m * HW + bn + tx * 4] = o4;
    }
}

// ---------------- plane transpose: [N][H][W] -> [N][W][H] -------------------
__global__ void transpose_kernel(const float* __restrict__ in, float* __restrict__ out)
{
    __shared__ float tile[32][33];
    int n = blockIdx.z;
    int h0 = blockIdx.y * 32, w0 = blockIdx.x * 32;
    const float* ip = in  + (size_t)n * HW;
    float*       op = out + (size_t)n * HW;
    int tx = threadIdx.x, ty = threadIdx.y;   // 32 x 8
#pragma unroll
    for (int r = 0; r < 32; r += 8)
        tile[ty + r][tx] = ip[(size_t)(h0 + ty + r) * LL + w0 + tx];
    __syncthreads();
#pragma unroll
    for (int r = 0; r < 32; r += 8)
        op[(size_t)(w0 + ty + r) * LL + h0 + tx] = tile[tx][ty + r];
}

// ---------------- energy: per (b,line) S[i,j] = sum_c Q[c,i] K[c,j] ---------
// Q/K layout: base + b*CQ*HW + c*HW + line*96 + i  (works for both H and W dir)
// grid: (B*96), block 256, dyn smem 2*64*97*4 = 49664
__global__ void energy_kernel(const float* __restrict__ Q, const float* __restrict__ K,
                              float* __restrict__ E, int maskDiag)
{
    extern __shared__ float sm[];
    float* Qs = sm;             // [64][97]
    float* Ks = sm + 64 * 97;
    int bl = blockIdx.x;
    int b = bl / LL, line = bl % LL;
    size_t base = (size_t)b * CQq * HW + (size_t)line * LL;
    int t = threadIdx.x;
    for (int idx = t; idx < 64 * LL; idx += 256) {
        int c = idx / LL, i = idx % LL;
        Qs[c * 97 + i] = Q[base + (size_t)c * HW + i];
        Ks[c * 97 + i] = K[base + (size_t)c * HW + i];
    }
    __syncthreads();
    int tx = t & 15, ty = t >> 4;
    float acc[6][6];
#pragma unroll
    for (int a = 0; a < 6; a++)
#pragma unroll
        for (int b2 = 0; b2 < 6; b2++) acc[a][b2] = 0.f;

    for (int c = 0; c < 64; c++) {
        float qv[6], kv[6];
#pragma unroll
        for (int a = 0; a < 6; a++)  qv[a]  = Qs[c * 97 + ty + 16 * a];
#pragma unroll
        for (int b2 = 0; b2 < 6; b2++) kv[b2] = Ks[c * 97 + tx + 16 * b2];
#pragma unroll
        for (int a = 0; a < 6; a++)
#pragma unroll
            for (int b2 = 0; b2 < 6; b2++) acc[a][b2] += qv[a] * kv[b2];
    }
    float* Eb = E + (size_t)bl * LL * LL;
#pragma unroll
    for (int a = 0; a < 6; a++) {
        int i = ty + 16 * a;
#pragma unroll
        for (int b2 = 0; b2 < 6; b2++) {
            int j = tx + 16 * b2;
            Eb[(size_t)i * LL + j] = (maskDiag && i == j) ? -1e30f : acc[a][b2];
        }
    }
}

// ---------------- joint softmax over concat(eH row, eW row), one warp/pixel -
__global__ void softmax_kernel()
{
    int dir  = blockIdx.y;
    int warp = (blockIdx.x * blockDim.x + threadIdx.x) >> 5;
    int lane = threadIdx.x & 31;
    int b  = warp / HW;
    int hw = warp % HW;
    int h = hw / LL, w = hw % LL;
    float* rH = &g_eH[dir][(((size_t)b * LL + w) * LL + h) * LL];
    float* rW = &g_eW[dir][(((size_t)b * LL + h) * LL + w) * LL];
    float v[6];
#pragma unroll
    for (int i = 0; i < 3; i++) v[i]     = rH[lane + 32 * i];
#pragma unroll
    for (int i = 0; i < 3; i++) v[3 + i] = rW[lane + 32 * i];
    float m = v[0];
#pragma unroll
    for (int i = 1; i < 6; i++) m = fmaxf(m, v[i]);
#pragma unroll
    for (int o = 16; o > 0; o >>= 1) m = fmaxf(m, __shfl_xor_sync(0xffffffffu, m, o));
    float s = 0.f;
#pragma unroll
    for (int i = 0; i < 6; i++) { v[i] = __expf(v[i] - m); s += v[i]; }
#pragma unroll
    for (int o = 16; o > 0; o >>= 1) s += __shfl_xor_sync(0xffffffffu, s, o);
    float inv = 1.f / s;
#pragma unroll
    for (int i = 0; i < 3; i++) rH[lane + 32 * i] = v[i]     * inv;
#pragma unroll
    for (int i = 0; i < 3; i++) rW[lane + 32 * i] = v[3 + i] * inv;
}

// ---------------- apply: per (b,line): O[c,i] = sum_k V[c,k] A[i,k] ---------
// V element (c,k)   at Vb[((b*C + c)*96 + line)*96 + k]
// A element (i,k)   at Ab[ bl*96*96 + i*96 + k ]
// O element (c,i)   at Ob[ (bl*C + c)*96 + i ]
// grid: (C/64, B*96), block 256, dyn smem (96+64)*97*4 = 62080
__global__ void apply_kernel(const float* __restrict__ Vb, const float* __restrict__ Ab,
                             float* __restrict__ Ob)
{
    extern __shared__ float sm[];
    float* As_ = sm;              // [96][97]
    float* Vs  = sm + 96 * 97;    // [64][97]
    int ct0 = blockIdx.x * 64;
    int bl  = blockIdx.y;
    int b = bl / LL, line = bl % LL;
    int t = threadIdx.x;

    const float* Ap = Ab + (size_t)bl * LL * LL;
    for (int idx = t; idx < LL * LL; idx += 256)
        As_[(idx / LL) * 97 + (idx % LL)] = Ap[idx];

    const float* Vp = Vb + ((size_t)(b * Cc + ct0) * LL + line) * LL;
    for (int idx = t; idx < 64 * LL; idx += 256) {
        int c = idx / LL, k = idx % LL;
        Vs[c * 97 + k] = Vp[(size_t)c * HW + k];
    }
    __syncthreads();

    int tx = t & 31, ty = t >> 5;   // tx -> i = tx + 32*j (3), ty -> c = ty*8 + i (8)
    float acc[8][3];
#pragma unroll
    for (int i = 0; i < 8; i++)
#pragma unroll
        for (int j = 0; j < 3; j++) acc[i][j] = 0.f;

    for (int k = 0; k < LL; k++) {
        float av[3];
#pragma unroll
        for (int j = 0; j < 3; j++) av[j] = As_[(tx + 32 * j) * 97 + k];
        float vv[8];
#pragma unroll
        for (int i = 0; i < 8; i++) vv[i] = Vs[(ty * 8 + i) * 97 + k];
#pragma unroll
        for (int i = 0; i < 8; i++)
#pragma unroll
            for (int j = 0; j < 3; j++) acc[i][j] += vv[i] * av[j];
    }
    float* Op = Ob + ((size_t)bl * Cc + ct0) * LL;
#pragma unroll
    for (int i = 0; i < 8; i++)
#pragma unroll
        for (int j = 0; j < 3; j++)
            Op[(size_t)(ty * 8 + i) * LL + tx + 32 * j] = acc[i][j];
}

// ---------------- final: out = gamma*(tH^T + tW) + residual -----------------
// grid: (W/32, H/32, 2*B*C), block (32,8)
__global__ void final_kernel(const float* __restrict__ x, const float* __restrict__ y,
                             const float* __restrict__ gamma, float* __restrict__ out)
{
    __shared__ float tile[32][33];
    int z  = blockIdx.z;
    int o  = z >> 12;           // B*C = 4096
    int bc = z & 4095;
    int b  = bc >> 9;
    int c  = bc & 511;
    int h0 = blockIdx.y * 32, w0 = blockIdx.x * 32;
    float g = gamma[0];
    const float* res = (o == 0 ? x : y) + (size_t)bc * HW;
    const float* tH = g_tH[o];
    const float* tW = g_tW[o];
    int tx = threadIdx.x, ty = threadIdx.y;

#pragma unroll
    for (int r = 0; r < 32; r += 8) {
        int w = w0 + ty + r;
        tile[ty + r][tx] = tH[(((size_t)b * LL + w) * Cc + c) * LL + h0 + tx];
    }
    __syncthreads();
    float* op = out + (size_t)o * BCHW + (size_t)bc * HW;
#pragma unroll
    for (int r = 0; r < 32; r += 8) {
        int h = h0 + ty + r;
        size_t ro = (size_t)h * LL + w0 + tx;
        float tw = tW[(((size_t)b * LL + h) * Cc + c) * LL + w0 + tx];
        op[ro] = g * (tile[tx][ty + r] + tw) + res[ro];
    }
}

// ---------------------------------------------------------------------------
extern "C" void kernel_launch(void* const* d_in, const int* in_sizes, int n_in,
                              void* d_out, int out_size)
{
    const float* x     = (const float*)d_in[0];
    const float* y     = (const float*)d_in[1];
    const float* Wq    = (const float*)d_in[2];
    const float* bq    = (const float*)d_in[3];
    const float* Wk    = (const float*)d_in[4];
    const float* bk    = (const float*)d_in[5];
    const float* Wv    = (const float*)d_in[6];
    const float* bv    = (const float*)d_in[7];
    const float* gamma = (const float*)d_in[8];
    float* out = (float*)d_out;
    (void)in_sizes; (void)n_in; (void)out_size;

    float *q, *k, *qT, *kT, *v, *vT, *eH, *eW, *tH, *tW;
    cudaGetSymbolAddress((void**)&q,  g_q);
    cudaGetSymbolAddress((void**)&k,  g_k);
    cudaGetSymbolAddress((void**)&qT, g_qT);
    cudaGetSymbolAddress((void**)&kT, g_kT);
    cudaGetSymbolAddress((void**)&v,  g_v);
    cudaGetSymbolAddress((void**)&vT, g_vT);
    cudaGetSymbolAddress((void**)&eH, g_eH);
    cudaGetSymbolAddress((void**)&eW, g_eW);
    cudaGetSymbolAddress((void**)&tH, g_tH);
    cudaGetSymbolAddress((void**)&tW, g_tW);

    const int ESM = 2 * 64 * 97 * 4;          // 49664
    const int ASM = (96 + 64) * 97 * 4;       // 62080
    cudaFuncSetAttribute(energy_kernel, cudaFuncAttributeMaxDynamicSharedMemorySize, ESM);
    cudaFuncSetAttribute(apply_kernel,  cudaFuncAttributeMaxDynamicSharedMemorySize, ASM);

    float* q0 = q;            float* q1 = q  + BQHW;
    float* k0 = k;            float* k1 = k  + BQHW;
    float* qT0 = qT;          float* qT1 = qT + BQHW;
    float* kT0 = kT;          float* kT1 = kT + BQHW;
    float* v0 = v;            float* v1 = v  + BCHW;
    float* vT0 = vT;          float* vT1 = vT + BCHW;
    float* eH0 = eH;          float* eH1 = eH + ELN;
    float* eW0 = eW;          float* eW1 = eW + ELN;
    float* tH0 = tH;          float* tH1 = tH + BCHW;
    float* tW0 = tW;          float* tW1 = tW + BCHW;

    // 1) projections
    proj_kernel<<<dim3(144, 1, Bz), 256>>>(x, Wq, bq, q0, CQq);
    proj_kernel<<<dim3(144, 1, Bz), 256>>>(y, Wq, bq, q1, CQq);
    proj_kernel<<<dim3(144, 1, Bz), 256>>>(x, Wk, bk, k0, CQq);
    proj_kernel<<<dim3(144, 1, Bz), 256>>>(y, Wk, bk, k1, CQq);
    proj_kernel<<<dim3(144, 8, Bz), 256>>>(x, Wv, bv, v0, Cc);
    proj_kernel<<<dim3(144, 8, Bz), 256>>>(y, Wv, bv, v1, Cc);

    // 2) transposes (H<->W) for column-direction access
    dim3 tb(32, 8);
    transpose_kernel<<<dim3(3, 3, Bz * CQq), tb>>>(q0, qT0);
    transpose_kernel<<<dim3(3, 3, Bz * CQq), tb>>>(q1, qT1);
    transpose_kernel<<<dim3(3, 3, Bz * CQq), tb>>>(k0, kT0);
    transpose_kernel<<<dim3(3, 3, Bz * CQq), tb>>>(k1, kT1);
    transpose_kernel<<<dim3(3, 3, Bz * Cc),  tb>>>(v0, vT0);
    transpose_kernel<<<dim3(3, 3, Bz * Cc),  tb>>>(v1, vT1);

    // 3) energies  (dir0: q from x, keys from y; dir1: q from y, keys from x)
    energy_kernel<<<Bz * LL, 256, ESM>>>(qT0, kT1, eH0, 1);
    energy_kernel<<<Bz * LL, 256, ESM>>>(qT1, kT0, eH1, 1);
    energy_kernel<<<Bz * LL, 256, ESM>>>(q0,  k1,  eW0, 0);
    energy_kernel<<<Bz * LL, 256, ESM>>>(q1,  k0,  eW1, 0);

    // 4) joint softmax (in place -> attention)
    softmax_kernel<<<dim3(9216, 2), 256>>>();

    // 5) applies: out1 = vx with att_yx(dir1); out2 = vy with att_xy(dir0)
    apply_kernel<<<dim3(8, Bz * LL), 256, ASM>>>(vT0, eH1, tH0);
    apply_kernel<<<dim3(8, Bz * LL), 256, ASM>>>(v0,  eW1, tW0);
    apply_kernel<<<dim3(8, Bz * LL), 256, ASM>>>(vT1, eH0, tH1);
    apply_kernel<<<dim3(8, Bz * LL), 256, ASM>>>(v1,  eW0, tW1);

    // 6) combine + residual
    final_kernel<<<dim3(3, 3, 2 * Bz * Cc), tb>>>(x, y, gamma, out);
}

// round 2
// speedup vs baseline: 1.2864x; 1.2864x over previous
#include <cuda_runtime.h>
#include <math.h>

// Problem constants
#define Bz   8
#define Cc   512
#define CQq  64
#define LL   96           // H == W == 96
#define HW   9216         // 96*96
#define BCHW 37748736     // 8*512*9216
#define BQKHW 9437184     // 8*128*9216 (stacked q||k)
#define ELN  7077888      // 8*96*96*96

// ---------------- scratch (device globals; allocation-free rule) ------------
__device__ float g_qk [2][BQKHW];  // [B][128][H][W]: ch 0..63 = q, 64..127 = k
__device__ float g_qkT[2][BQKHW];  // [B][128][W][H]
__device__ float g_v [2][BCHW];    // [B][C][H][W]
__device__ float g_vT[2][BCHW];    // [B][C][W][H]
__device__ float g_eH[2][ELN];     // energies->att  [B][W][H][Hk]
__device__ float g_eW[2][ELN];     // [B][H][W][Wk]
__device__ float g_tH[2][BCHW];    // applyH out  [B][W][C][H]
__device__ float g_tW[2][BCHW];    // applyW out  [B][H][C][W]
__device__ float g_Wqk[128 * 512];
__device__ float g_bqk[128];

// ---------------- stack Wq||Wk -----------------------------------------------
__global__ void concat_w_kernel(const float* __restrict__ Wq, const float* __restrict__ bq,
                                const float* __restrict__ Wk, const float* __restrict__ bk)
{
    int t = blockIdx.x * blockDim.x + threadIdx.x;
    const int n = 64 * 512;
    if (t < n) { g_Wqk[t] = Wq[t]; g_Wqk[n + t] = Wk[t]; }
    if (t < 64) { g_bqk[t] = bq[t]; g_bqk[64 + t] = bk[t]; }
}

// ---------------- 1x1 conv GEMM: out[b,m,n] = sum_k W[m,k] in[b,k,n] + bias[m]
// 128x128 tile, 256 threads, 8x8 per thread. grid (HW/128, Cout/128, B)
__global__ __launch_bounds__(256, 2)
void proj128_kernel(const float* __restrict__ in, const float* __restrict__ Wm,
                    const float* __restrict__ bias, float* __restrict__ out, int Cout)
{
    __shared__ float As[16][132];   // [k][m], stride 132 (16B-aligned rows)
    __shared__ float Bs[16][128];   // [k][n]

    int b  = blockIdx.z;
    int bm = blockIdx.y * 128;
    int bn = blockIdx.x * 128;
    int t  = threadIdx.x;
    int tx = t & 15, ty = t >> 4;

    const float* inb = in + (size_t)b * Cc * HW;

    float acc[8][8];
#pragma unroll
    for (int i = 0; i < 8; i++)
#pragma unroll
        for (int j = 0; j < 8; j++) acc[i][j] = 0.f;

    for (int k0 = 0; k0 < Cc; k0 += 16) {
        // A tile: W[bm+m][k0+kk] -> As[kk][m]; 2048 floats, float4 per thread x2
#pragma unroll
        for (int r = 0; r < 2; r++) {
            int i = t + 256 * r;
            int m = i >> 2, kq = (i & 3) * 4;
            float4 w4 = *(const float4*)&Wm[(size_t)(bm + m) * Cc + k0 + kq];
            As[kq + 0][m] = w4.x; As[kq + 1][m] = w4.y;
            As[kq + 2][m] = w4.z; As[kq + 3][m] = w4.w;
        }
        // B tile: in[(k0+kk)][bn+n] -> Bs[kk][n]; coalesced float4
#pragma unroll
        for (int r = 0; r < 2; r++) {
            int i = t + 256 * r;
            int kk = i >> 5, n4 = (i & 31) * 4;
            *(float4*)&Bs[kk][n4] = *(const float4*)&inb[(size_t)(k0 + kk) * HW + bn + n4];
        }
        __syncthreads();
#pragma unroll
        for (int kk = 0; kk < 16; kk++) {
            float a[8], bv[8];
            float4 a0 = *(const float4*)&As[kk][ty * 4];
            float4 a1 = *(const float4*)&As[kk][ty * 4 + 64];
            float4 b0 = *(const float4*)&Bs[kk][tx * 4];
            float4 b1 = *(const float4*)&Bs[kk][tx * 4 + 64];
            a[0] = a0.x; a[1] = a0.y; a[2] = a0.z; a[3] = a0.w;
            a[4] = a1.x; a[5] = a1.y; a[6] = a1.z; a[7] = a1.w;
            bv[0] = b0.x; bv[1] = b0.y; bv[2] = b0.z; bv[3] = b0.w;
            bv[4] = b1.x; bv[5] = b1.y; bv[6] = b1.z; bv[7] = b1.w;
#pragma unroll
            for (int i = 0; i < 8; i++)
#pragma unroll
                for (int j = 0; j < 8; j++) acc[i][j] += a[i] * bv[j];
        }
        __syncthreads();
    }
    // epilogue
#pragma unroll
    for (int i = 0; i < 8; i++) {
        int m = bm + ty * 4 + (i & 3) + (i >> 2) * 64;
        float bi = bias[m];
        float* op = out + (size_t)b * Cout * HW + (size_t)m * HW + bn;
#pragma unroll
        for (int g = 0; g < 2; g++) {
            float4 o4 = make_float4(acc[i][g * 4 + 0] + bi, acc[i][g * 4 + 1] + bi,
                                    acc[i][g * 4 + 2] + bi, acc[i][g * 4 + 3] + bi);
            *(float4*)&op[tx * 4 + g * 64] = o4;
        }
    }
}

// ---------------- plane transpose: [N][H][W] -> [N][W][H] -------------------
__global__ void transpose_kernel(const float* __restrict__ in, float* __restrict__ out)
{
    __shared__ float tile[32][33];
    int n = blockIdx.z;
    int h0 = blockIdx.y * 32, w0 = blockIdx.x * 32;
    const float* ip = in  + (size_t)n * HW;
    float*       op = out + (size_t)n * HW;
    int tx = threadIdx.x, ty = threadIdx.y;   // 32 x 8
#pragma unroll
    for (int r = 0; r < 32; r += 8)
        tile[ty + r][tx] = ip[(size_t)(h0 + ty + r) * LL + w0 + tx];
    __syncthreads();
#pragma unroll
    for (int r = 0; r < 32; r += 8)
        op[(size_t)(w0 + ty + r) * LL + h0 + tx] = tile[tx][ty + r];
}

// ---------------- energy: per (b,line) S[i,j] = sum_c Q[c,i] K[c,j] ---------
// element: base + b*bstride + c*HW + line*96 + i
__global__ void energy_kernel(const float* __restrict__ Q, const float* __restrict__ K,
                              float* __restrict__ E, int maskDiag, size_t bstride)
{
    extern __shared__ float sm[];
    float* Qs = sm;             // [64][97]
    float* Ks = sm + 64 * 97;
    int bl = blockIdx.x;
    int b = bl / LL, line = bl % LL;
    size_t base = (size_t)b * bstride + (size_t)line * LL;
    int t = threadIdx.x;
    for (int idx = t; idx < 64 * LL; idx += 256) {
        int c = idx / LL, i = idx % LL;
        Qs[c * 97 + i] = Q[base + (size_t)c * HW + i];
        Ks[c * 97 + i] = K[base + (size_t)c * HW + i];
    }
    __syncthreads();
    int tx = t & 15, ty = t >> 4;
    float acc[6][6];
#pragma unroll
    for (int a = 0; a < 6; a++)
#pragma unroll
        for (int b2 = 0; b2 < 6; b2++) acc[a][b2] = 0.f;

    for (int c = 0; c < 64; c++) {
        float qv[6], kv[6];
#pragma unroll
        for (int a = 0; a < 6; a++)  qv[a]  = Qs[c * 97 + ty + 16 * a];
#pragma unroll
        for (int b2 = 0; b2 < 6; b2++) kv[b2] = Ks[c * 97 + tx + 16 * b2];
#pragma unroll
        for (int a = 0; a < 6; a++)
#pragma unroll
            for (int b2 = 0; b2 < 6; b2++) acc[a][b2] += qv[a] * kv[b2];
    }
    float* Eb = E + (size_t)bl * LL * LL;
#pragma unroll
    for (int a = 0; a < 6; a++) {
        int i = ty + 16 * a;
#pragma unroll
        for (int b2 = 0; b2 < 6; b2++) {
            int j = tx + 16 * b2;
            Eb[(size_t)i * LL + j] = (maskDiag && i == j) ? -1e30f : acc[a][b2];
        }
    }
}

// ---------------- joint softmax over concat(eH row, eW row), one warp/pixel -
__global__ void softmax_kernel()
{
    int dir  = blockIdx.y;
    int warp = (blockIdx.x * blockDim.x + threadIdx.x) >> 5;
    int lane = threadIdx.x & 31;
    int b  = warp / HW;
    int hw = warp % HW;
    int h = hw / LL, w = hw % LL;
    float* rH = &g_eH[dir][(((size_t)b * LL + w) * LL + h) * LL];
    float* rW = &g_eW[dir][(((size_t)b * LL + h) * LL + w) * LL];
    float v[6];
#pragma unroll
    for (int i = 0; i < 3; i++) v[i]     = rH[lane + 32 * i];
#pragma unroll
    for (int i = 0; i < 3; i++) v[3 + i] = rW[lane + 32 * i];
    float m = v[0];
#pragma unroll
    for (int i = 1; i < 6; i++) m = fmaxf(m, v[i]);
#pragma unroll
    for (int o = 16; o > 0; o >>= 1) m = fmaxf(m, __shfl_xor_sync(0xffffffffu, m, o));
    float s = 0.f;
#pragma unroll
    for (int i = 0; i < 6; i++) { v[i] = __expf(v[i] - m); s += v[i]; }
#pragma unroll
    for (int o = 16; o > 0; o >>= 1) s += __shfl_xor_sync(0xffffffffu, s, o);
    float inv = 1.f / s;
#pragma unroll
    for (int i = 0; i < 3; i++) rH[lane + 32 * i] = v[i]     * inv;
#pragma unroll
    for (int i = 0; i < 3; i++) rW[lane + 32 * i] = v[3 + i] * inv;
}

// ---------------- apply: per (b,line): O[c,i] = sum_k V[c,k] A[i,k] ---------
// V element (c,k) at Vb[((b*C + c)*96 + line)*96 + k]
// A element (i,k) at Ab[ bl*96*96 + i*96 + k ]
// O element (c,i) at Ob[ (bl*C + c)*96 + i ]
// grid: (C/128, B*96), 256 threads, 4x12 per thread. dyn smem 89600
__global__ __launch_bounds__(256, 2)
void apply_kernel(const float* __restrict__ Vb, const float* __restrict__ Ab,
                  float* __restrict__ Ob)
{
    extern __shared__ float sm[];
    float* As2 = sm;              // [96][100]  ([k][i])
    float* Vs  = sm + 96 * 100;   // [128][100] ([c][k])
    int ct0 = blockIdx.x * 128;
    int bl  = blockIdx.y;
    int b = bl / LL, line = bl % LL;
    int t = threadIdx.x;
    int tx = t & 7;    // i = tx*4 + 32g, g 0..2
    int ty = t >> 3;   // c = ty + 32m, m 0..3

    // A transpose load: [i][k] -> As2[k][i]
    const float* Ap = Ab + (size_t)bl * LL * LL;
    for (int idx = t; idx < LL * LL; idx += 256) {
        int i = idx / LL, k = idx % LL;
        As2[k * 100 + i] = Ap[idx];
    }
    // V direct load: [c][k] -> Vs[c][k], float4
    const float* Vp = Vb + ((size_t)(b * Cc + ct0) * LL + line) * LL;
#pragma unroll
    for (int r = 0; r < 12; r++) {
        int idx = t + 256 * r;
        int c = idx / 24, k4 = (idx % 24) * 4;
        *(float4*)&Vs[c * 100 + k4] = *(const float4*)&Vp[(size_t)c * HW + k4];
    }
    __syncthreads();

    float acc[4][12];
#pragma unroll
    for (int m = 0; m < 4; m++)
#pragma unroll
        for (int j = 0; j < 12; j++) acc[m][j] = 0.f;

#pragma unroll 2
    for (int k = 0; k < LL; k++) {
        float av[12];
#pragma unroll
        for (int g = 0; g < 3; g++) {
            float4 a4 = *(const float4*)&As2[k * 100 + tx * 4 + 32 * g];
            av[g * 4 + 0] = a4.x; av[g * 4 + 1] = a4.y;
            av[g * 4 + 2] = a4.z; av[g * 4 + 3] = a4.w;
        }
        float vv[4];
#pragma unroll
        for (int m = 0; m < 4; m++) vv[m] = Vs[(ty + 32 * m) * 100 + k];
#pragma unroll
        for (int m = 0; m < 4; m++)
#pragma unroll
            for (int j = 0; j < 12; j++) acc[m][j] += vv[m] * av[j];
    }

    float* Op = Ob + ((size_t)bl * Cc + ct0) * LL;
#pragma unroll
    for (int m = 0; m < 4; m++) {
        float* orow = Op + (size_t)(ty + 32 * m) * LL;
#pragma unroll
        for (int g = 0; g < 3; g++) {
            float4 o4 = make_float4(acc[m][g * 4 + 0], acc[m][g * 4 + 1],
                                    acc[m][g * 4 + 2], acc[m][g * 4 + 3]);
            *(float4*)&orow[tx * 4 + 32 * g] = o4;
        }
    }
}

// ---------------- final: out = gamma*(tH^T + tW) + residual -----------------
__global__ void final_kernel(const float* __restrict__ x, const float* __restrict__ y,
                             const float* __restrict__ gamma, float* __restrict__ out)
{
    __shared__ float tile[32][33];
    int z  = blockIdx.z;
    int o  = z >> 12;           // B*C = 4096
    int bc = z & 4095;
    int b  = bc >> 9;
    int c  = bc & 511;
    int h0 = blockIdx.y * 32, w0 = blockIdx.x * 32;
    float g = gamma[0];
    const float* res = (o == 0 ? x : y) + (size_t)bc * HW;
    const float* tH = g_tH[o];
    const float* tW = g_tW[o];
    int tx = threadIdx.x, ty = threadIdx.y;

#pragma unroll
    for (int r = 0; r < 32; r += 8) {
        int w = w0 + ty + r;
        tile[ty + r][tx] = tH[(((size_t)b * LL + w) * Cc + c) * LL + h0 + tx];
    }
    __syncthreads();
    float* op = out + (size_t)o * BCHW + (size_t)bc * HW;
#pragma unroll
    for (int r = 0; r < 32; r += 8) {
        int h = h0 + ty + r;
        size_t ro = (size_t)h * LL + w0 + tx;
        float tw = tW[(((size_t)b * LL + h) * Cc + c) * LL + w0 + tx];
        op[ro] = g * (tile[tx][ty + r] + tw) + res[ro];
    }
}

// ---------------------------------------------------------------------------
extern "C" void kernel_launch(void* const* d_in, const int* in_sizes, int n_in,
                              void* d_out, int out_size)
{
    const float* x     = (const float*)d_in[0];
    const float* y     = (const float*)d_in[1];
    const float* Wq    = (const float*)d_in[2];
    const float* bq    = (const float*)d_in[3];
    const float* Wk    = (const float*)d_in[4];
    const float* bk    = (const float*)d_in[5];
    const float* Wv    = (const float*)d_in[6];
    const float* bv    = (const float*)d_in[7];
    const float* gamma = (const float*)d_in[8];
    float* out = (float*)d_out;
    (void)in_sizes; (void)n_in; (void)out_size;

    float *qk, *qkT, *v, *vT, *eH, *eW, *tH, *tW, *Wqk, *bqk;
    cudaGetSymbolAddress((void**)&qk,  g_qk);
    cudaGetSymbolAddress((void**)&qkT, g_qkT);
    cudaGetSymbolAddress((void**)&v,   g_v);
    cudaGetSymbolAddress((void**)&vT,  g_vT);
    cudaGetSymbolAddress((void**)&eH,  g_eH);
    cudaGetSymbolAddress((void**)&eW,  g_eW);
    cudaGetSymbolAddress((void**)&tH,  g_tH);
    cudaGetSymbolAddress((void**)&tW,  g_tW);
    cudaGetSymbolAddress((void**)&Wqk, g_Wqk);
    cudaGetSymbolAddress((void**)&bqk, g_bqk);

    const int ESM = 2 * 64 * 97 * 4;               // 49664
    const int ASM = (96 * 100 + 128 * 100) * 4;    // 89600
    cudaFuncSetAttribute(energy_kernel, cudaFuncAttributeMaxDynamicSharedMemorySize, ESM);
    cudaFuncSetAttribute(apply_kernel,  cudaFuncAttributeMaxDynamicSharedMemorySize, ASM);

    float* qk0  = qk;          float* qk1  = qk  + BQKHW;
    float* qkT0 = qkT;         float* qkT1 = qkT + BQKHW;
    float* v0 = v;             float* v1 = v  + BCHW;
    float* vT0 = vT;           float* vT1 = vT + BCHW;
    float* eH0 = eH;           float* eH1 = eH + ELN;
    float* eW0 = eW;           float* eW1 = eW + ELN;
    float* tH0 = tH;           float* tH1 = tH + BCHW;
    float* tW0 = tW;           float* tW1 = tW + BCHW;

    // 0) stack Wq||Wk
    concat_w_kernel<<<128, 256>>>(Wq, bq, Wk, bk);

    // 1) projections (q&k fused: Cout=128; v: Cout=512)
    proj128_kernel<<<dim3(72, 1, Bz), 256>>>(x, Wqk, bqk, qk0, 128);
    proj128_kernel<<<dim3(72, 1, Bz), 256>>>(y, Wqk, bqk, qk1, 128);
    proj128_kernel<<<dim3(72, 4, Bz), 256>>>(x, Wv, bv, v0, Cc);
    proj128_kernel<<<dim3(72, 4, Bz), 256>>>(y, Wv, bv, v1, Cc);

    // 2) transposes (H<->W)
    dim3 tb(32, 8);
    transpose_kernel<<<dim3(3, 3, Bz * 128), tb>>>(qk0, qkT0);
    transpose_kernel<<<dim3(3, 3, Bz * 128), tb>>>(qk1, qkT1);
    transpose_kernel<<<dim3(3, 3, Bz * Cc),  tb>>>(v0, vT0);
    transpose_kernel<<<dim3(3, 3, Bz * Cc),  tb>>>(v1, vT1);

    // 3) energies (dir0: q from x, keys from y; dir1: q from y, keys from x)
    const size_t QKB = (size_t)128 * HW;
    energy_kernel<<<Bz * LL, 256, ESM>>>(qkT0,            qkT1 + 64 * HW, eH0, 1, QKB);
    energy_kernel<<<Bz * LL, 256, ESM>>>(qkT1,            qkT0 + 64 * HW, eH1, 1, QKB);
    energy_kernel<<<Bz * LL, 256, ESM>>>(qk0,             qk1  + 64 * HW, eW0, 0, QKB);
    energy_kernel<<<Bz * LL, 256, ESM>>>(qk1,             qk0  + 64 * HW, eW1, 0, QKB);

    // 4) joint softmax (in place -> attention)
    softmax_kernel<<<dim3(9216, 2), 256>>>();

    // 5) applies: out1 = vx with att_yx(dir1); out2 = vy with att_xy(dir0)
    apply_kernel<<<dim3(4, Bz * LL), 256, ASM>>>(vT0, eH1, tH0);
    apply_kernel<<<dim3(4, Bz * LL), 256, ASM>>>(v0,  eW1, tW0);
    apply_kernel<<<dim3(4, Bz * LL), 256, ASM>>>(vT1, eH0, tH1);
    apply_kernel<<<dim3(4, Bz * LL), 256, ASM>>>(v1,  eW0, tW1);

    // 6) combine + residual
    final_kernel<<<dim3(3, 3, 2 * Bz * Cc), tb>>>(x, y, gamma, out);
}

// round 3
// speedup vs baseline: 1.9397x; 1.5079x over previous
#include <cuda_runtime.h>
#include <math.h>
#include <stdint.h>

// Problem constants
#define Bz   8
#define Cc   512
#define CQq  64
#define LL   96           // H == W == 96
#define HW   9216         // 96*96
#define BCHW 37748736     // 8*512*9216
#define BQKHW 9437184     // 8*128*9216 (stacked q||k)
#define ELN  7077888      // 8*96*96*96

// ---------------- scratch (device globals; allocation-free rule) ------------
__device__ float g_qk [2][BQKHW];  // [B][128][H][W]: ch 0..63 = q, 64..127 = k
__device__ float g_qkT[2][BQKHW];  // [B][128][W][H]
__device__ float g_v [2][BCHW];    // [B][C][H][W]
__device__ float g_vT[2][BCHW];    // [B][C][W][H]
__device__ float g_eH[2][ELN];     // energies->att  [B][W][H][Hk]
__device__ float g_eW[2][ELN];     // [B][H][W][Wk]
__device__ float g_tH[2][BCHW];    // applyH out  [B][W][C][H]
__device__ float g_tW[2][BCHW];    // applyW out  [B][H][C][W]
__device__ float g_Wqk[128 * 512];
__device__ float g_bqk[128];

// ---------------- helpers ----------------------------------------------------
__device__ __forceinline__ uint32_t f2tf32(float f)
{
    uint32_t r;
    asm("cvt.rna.tf32.f32 %0, %1;" : "=r"(r) : "f"(f));
    return r;
}

__device__ __forceinline__ void mma_tf32(float& c0, float& c1, float& c2, float& c3,
                                         uint32_t a0, uint32_t a1, uint32_t a2, uint32_t a3,
                                         uint32_t b0, uint32_t b1)
{
    asm volatile(
        "mma.sync.aligned.m16n8k8.row.col.f32.tf32.tf32.f32 "
        "{%0,%1,%2,%3}, {%4,%5,%6,%7}, {%8,%9}, {%0,%1,%2,%3};"
        : "+f"(c0), "+f"(c1), "+f"(c2), "+f"(c3)
        : "r"(a0), "r"(a1), "r"(a2), "r"(a3), "r"(b0), "r"(b1));
}

// ---------------- stack Wq||Wk -----------------------------------------------
__global__ void concat_w_kernel(const float* __restrict__ Wq, const float* __restrict__ bq,
                                const float* __restrict__ Wk, const float* __restrict__ bk)
{
    int t = blockIdx.x * blockDim.x + threadIdx.x;
    const int n = 64 * 512;
    if (t < n) { g_Wqk[t] = Wq[t]; g_Wqk[n + t] = Wk[t]; }
    if (t < 64) { g_bqk[t] = bq[t]; g_bqk[64 + t] = bk[t]; }
}

// ---------------- 1x1 conv GEMM via tf32 tensor cores ------------------------
// out[b,m,n] = sum_k W[m,k] in[b,k,n] + bias[m]
// 128(m) x 128(n) block tile, K=512 in steps of 16; 8 warps = 2(m) x 4(n),
// warp tile 64x32 = 4x4 m16n8 fragments.
__global__ __launch_bounds__(256)
void proj_tf32_kernel(const float* __restrict__ in, const float* __restrict__ Wm,
                      const float* __restrict__ bias, float* __restrict__ out, int Cout)
{
    __shared__ uint32_t As[16][136];   // [k][m] tf32, stride 136 (8 mod 32)
    __shared__ uint32_t Bs[16][136];   // [k][n] tf32

    int b  = blockIdx.z;
    int bm = blockIdx.y * 128;
    int bn = blockIdx.x * 128;
    int t  = threadIdx.x;
    int warp = t >> 5, lane = t & 31;
    int g = lane >> 2, tg = lane & 3;
    int mw = (warp >> 2) * 64;
    int nw = (warp & 3) * 32;

    const float* inb = in + (size_t)b * Cc * HW;

    float c[4][4][4];
#pragma unroll
    for (int i = 0; i < 4; i++)
#pragma unroll
        for (int j = 0; j < 4; j++)
#pragma unroll
            for (int r = 0; r < 4; r++) c[i][j][r] = 0.f;

    for (int k0 = 0; k0 < Cc; k0 += 16) {
        // A: W[bm+m][k0+kq..] -> As[k][m]
#pragma unroll
        for (int r = 0; r < 2; r++) {
            int i = t + 256 * r;
            int m = i >> 2, kq = (i & 3) * 4;
            float4 w4 = *(const float4*)&Wm[(size_t)(bm + m) * Cc + k0 + kq];
            As[kq + 0][m] = f2tf32(w4.x);
            As[kq + 1][m] = f2tf32(w4.y);
            As[kq + 2][m] = f2tf32(w4.z);
            As[kq + 3][m] = f2tf32(w4.w);
        }
        // B: in[(k0+kk)][bn+n] -> Bs[kk][n]
#pragma unroll
        for (int r = 0; r < 2; r++) {
            int i = t + 256 * r;
            int kk = i >> 5, n4 = (i & 31) * 4;
            float4 b4 = *(const float4*)&inb[(size_t)(k0 + kk) * HW + bn + n4];
            uint4 u4 = make_uint4(f2tf32(b4.x), f2tf32(b4.y), f2tf32(b4.z), f2tf32(b4.w));
            *(uint4*)&Bs[kk][n4] = u4;
        }
        __syncthreads();
#pragma unroll
        for (int kk = 0; kk < 16; kk += 8) {
            uint32_t a[4][4], bb[4][2];
#pragma unroll
            for (int mt = 0; mt < 4; mt++) {
                int m0 = mw + mt * 16;
                a[mt][0] = As[kk + tg    ][m0 + g];
                a[mt][1] = As[kk + tg    ][m0 + g + 8];
                a[mt][2] = As[kk + tg + 4][m0 + g];
                a[mt][3] = As[kk + tg + 4][m0 + g + 8];
            }
#pragma unroll
            for (int nt = 0; nt < 4; nt++) {
                int n0 = nw + nt * 8;
                bb[nt][0] = Bs[kk + tg    ][n0 + g];
                bb[nt][1] = Bs[kk + tg + 4][n0 + g];
            }
#pragma unroll
            for (int mt = 0; mt < 4; mt++)
#pragma unroll
                for (int nt = 0; nt < 4; nt++)
                    mma_tf32(c[mt][nt][0], c[mt][nt][1], c[mt][nt][2], c[mt][nt][3],
                             a[mt][0], a[mt][1], a[mt][2], a[mt][3],
                             bb[nt][0], bb[nt][1]);
        }
        __syncthreads();
    }
    // epilogue: c0:(g, tg*2) c1:(g, tg*2+1) c2:(g+8, tg*2) c3:(g+8, tg*2+1)
#pragma unroll
    for (int mt = 0; mt < 4; mt++) {
        int m0 = bm + mw + mt * 16 + g;
        float bi0 = bias[m0];
        float bi1 = bias[m0 + 8];
        float* op0 = out + (size_t)b * Cout * HW + (size_t)m0 * HW + bn;
        float* op1 = op0 + (size_t)8 * HW;
#pragma unroll
        for (int nt = 0; nt < 4; nt++) {
            int n0 = nw + nt * 8 + tg * 2;
            *(float2*)&op0[n0] = make_float2(c[mt][nt][0] + bi0, c[mt][nt][1] + bi0);
            *(float2*)&op1[n0] = make_float2(c[mt][nt][2] + bi1, c[mt][nt][3] + bi1);
        }
    }
}

// ---------------- plane transpose: [N][H][W] -> [N][W][H] -------------------
__global__ void transpose_kernel(const float* __restrict__ in, float* __restrict__ out)
{
    __shared__ float tile[32][33];
    int n = blockIdx.z;
    int h0 = blockIdx.y * 32, w0 = blockIdx.x * 32;
    const float* ip = in  + (size_t)n * HW;
    float*       op = out + (size_t)n * HW;
    int tx = threadIdx.x, ty = threadIdx.y;   // 32 x 8
#pragma unroll
    for (int r = 0; r < 32; r += 8)
        tile[ty + r][tx] = ip[(size_t)(h0 + ty + r) * LL + w0 + tx];
    __syncthreads();
#pragma unroll
    for (int r = 0; r < 32; r += 8)
        op[(size_t)(w0 + ty + r) * LL + h0 + tx] = tile[tx][ty + r];
}

// ---------------- energy: per (b,line) S[i,j] = sum_c Q[c,i] K[c,j] ---------
__global__ void energy_kernel(const float* __restrict__ Q, const float* __restrict__ K,
                              float* __restrict__ E, int maskDiag, size_t bstride)
{
    extern __shared__ float sm[];
    float* Qs = sm;             // [64][97]
    float* Ks = sm + 64 * 97;
    int bl = blockIdx.x;
    int b = bl / LL, line = bl % LL;
    size_t base = (size_t)b * bstride + (size_t)line * LL;
    int t = threadIdx.x;
    for (int idx = t; idx < 64 * LL; idx += 256) {
        int c = idx / LL, i = idx % LL;
        Qs[c * 97 + i] = Q[base + (size_t)c * HW + i];
        Ks[c * 97 + i] = K[base + (size_t)c * HW + i];
    }
    __syncthreads();
    int tx = t & 15, ty = t >> 4;
    float acc[6][6];
#pragma unroll
    for (int a = 0; a < 6; a++)
#pragma unroll
        for (int b2 = 0; b2 < 6; b2++) acc[a][b2] = 0.f;

    for (int c = 0; c < 64; c++) {
        float qv[6], kv[6];
#pragma unroll
        for (int a = 0; a < 6; a++)  qv[a]  = Qs[c * 97 + ty + 16 * a];
#pragma unroll
        for (int b2 = 0; b2 < 6; b2++) kv[b2] = Ks[c * 97 + tx + 16 * b2];
#pragma unroll
        for (int a = 0; a < 6; a++)
#pragma unroll
            for (int b2 = 0; b2 < 6; b2++) acc[a][b2] += qv[a] * kv[b2];
    }
    float* Eb = E + (size_t)bl * LL * LL;
#pragma unroll
    for (int a = 0; a < 6; a++) {
        int i = ty + 16 * a;
#pragma unroll
        for (int b2 = 0; b2 < 6; b2++) {
            int j = tx + 16 * b2;
            Eb[(size_t)i * LL + j] = (maskDiag && i == j) ? -1e30f : acc[a][b2];
        }
    }
}

// ---------------- joint softmax over concat(eH row, eW row), one warp/pixel -
__global__ void softmax_kernel()
{
    int dir  = blockIdx.y;
    int warp = (blockIdx.x * blockDim.x + threadIdx.x) >> 5;
    int lane = threadIdx.x & 31;
    int b  = warp / HW;
    int hw = warp % HW;
    int h = hw / LL, w = hw % LL;
    float* rH = &g_eH[dir][(((size_t)b * LL + w) * LL + h) * LL];
    float* rW = &g_eW[dir][(((size_t)b * LL + h) * LL + w) * LL];
    float v[6];
#pragma unroll
    for (int i = 0; i < 3; i++) v[i]     = rH[lane + 32 * i];
#pragma unroll
    for (int i = 0; i < 3; i++) v[3 + i] = rW[lane + 32 * i];
    float m = v[0];
#pragma unroll
    for (int i = 1; i < 6; i++) m = fmaxf(m, v[i]);
#pragma unroll
    for (int o = 16; o > 0; o >>= 1) m = fmaxf(m, __shfl_xor_sync(0xffffffffu, m, o));
    float s = 0.f;
#pragma unroll
    for (int i = 0; i < 6; i++) { v[i] = __expf(v[i] - m); s += v[i]; }
#pragma unroll
    for (int o = 16; o > 0; o >>= 1) s += __shfl_xor_sync(0xffffffffu, s, o);
    float inv = 1.f / s;
#pragma unroll
    for (int i = 0; i < 3; i++) rH[lane + 32 * i] = v[i]     * inv;
#pragma unroll
    for (int i = 0; i < 3; i++) rW[lane + 32 * i] = v[3 + i] * inv;
}

// ---------------- apply via tf32 tensor cores --------------------------------
// per (b,line): O[c,i] = sum_k V[c,k] A[i,k]
// M=128(c tile), N=96(i), K=96. 8 warps = 2(m) x 4(n), warp tile 64x24.
// dyn smem: Vs_t[96][136] + Bs[96][104] (uint32 tf32) = 92160 B
__global__ __launch_bounds__(256)
void apply_tf32_kernel(const float* __restrict__ Vb, const float* __restrict__ Ab,
                       float* __restrict__ Ob)
{
    extern __shared__ uint32_t smu[];
    uint32_t* Vs = smu;               // [k][c] stride 136
    uint32_t* As2 = smu + 96 * 136;   // [k][i] stride 104
    int ct0 = blockIdx.x * 128;
    int bl  = blockIdx.y;
    int b = bl / LL, line = bl % LL;
    int t = threadIdx.x;
    int warp = t >> 5, lane = t & 31;
    int g = lane >> 2, tg = lane & 3;
    int mw = (warp >> 2) * 64;
    int nw = (warp & 3) * 24;

    // V: [c][k] (k contiguous) -> Vs[k][c], tf32
    const float* Vp = Vb + ((size_t)(b * Cc + ct0) * LL + line) * LL;
#pragma unroll
    for (int r = 0; r < 12; r++) {
        int idx = t + 256 * r;
        int cI = idx / 24, k4 = (idx % 24) * 4;
        float4 v4 = *(const float4*)&Vp[(size_t)cI * HW + k4];
        Vs[(k4 + 0) * 136 + cI] = f2tf32(v4.x);
        Vs[(k4 + 1) * 136 + cI] = f2tf32(v4.y);
        Vs[(k4 + 2) * 136 + cI] = f2tf32(v4.z);
        Vs[(k4 + 3) * 136 + cI] = f2tf32(v4.w);
    }
    // A: [i][k] -> As2[k][i], tf32
    const float* Ap = Ab + (size_t)bl * LL * LL;
    for (int idx = t; idx < LL * LL; idx += 256) {
        int i = idx / LL, k = idx % LL;
        As2[k * 104 + i] = f2tf32(Ap[idx]);
    }
    __syncthreads();

    float c[4][3][4];
#pragma unroll
    for (int i = 0; i < 4; i++)
#pragma unroll
        for (int j = 0; j < 3; j++)
#pragma unroll
            for (int r = 0; r < 4; r++) c[i][j][r] = 0.f;

#pragma unroll
    for (int kk = 0; kk < LL; kk += 8) {
        uint32_t a[4][4], bb[3][2];
#pragma unroll
        for (int mt = 0; mt < 4; mt++) {
            int m0 = mw + mt * 16;
            a[mt][0] = Vs[(kk + tg    ) * 136 + m0 + g];
            a[mt][1] = Vs[(kk + tg    ) * 136 + m0 + g + 8];
            a[mt][2] = Vs[(kk + tg + 4) * 136 + m0 + g];
            a[mt][3] = Vs[(kk + tg + 4) * 136 + m0 + g + 8];
        }
#pragma unroll
        for (int nt = 0; nt < 3; nt++) {
            int n0 = nw + nt * 8;
            bb[nt][0] = As2[(kk + tg    ) * 104 + n0 + g];
            bb[nt][1] = As2[(kk + tg + 4) * 104 + n0 + g];
        }
#pragma unroll
        for (int mt = 0; mt < 4; mt++)
#pragma unroll
            for (int nt = 0; nt < 3; nt++)
                mma_tf32(c[mt][nt][0], c[mt][nt][1], c[mt][nt][2], c[mt][nt][3],
                         a[mt][0], a[mt][1], a[mt][2], a[mt][3],
                         bb[nt][0], bb[nt][1]);
    }

    float* Op = Ob + ((size_t)bl * Cc + ct0) * LL;
#pragma unroll
    for (int mt = 0; mt < 4; mt++) {
        int m0 = mw + mt * 16 + g;
        float* o0 = Op + (size_t)m0 * LL;
        float* o1 = o0 + (size_t)8 * LL;
#pragma unroll
        for (int nt = 0; nt < 3; nt++) {
            int n0 = nw + nt * 8 + tg * 2;
            *(float2*)&o0[n0] = make_float2(c[mt][nt][0], c[mt][nt][1]);
            *(float2*)&o1[n0] = make_float2(c[mt][nt][2], c[mt][nt][3]);
        }
    }
}

// ---------------- final: out = gamma*(tH^T + tW) + residual -----------------
__global__ void final_kernel(const float* __restrict__ x, const float* __restrict__ y,
                             const float* __restrict__ gamma, float* __restrict__ out)
{
    __shared__ float tile[32][33];
    int z  = blockIdx.z;
    int o  = z >> 12;           // B*C = 4096
    int bc = z & 4095;
    int b  = bc >> 9;
    int c  = bc & 511;
    int h0 = blockIdx.y * 32, w0 = blockIdx.x * 32;
    float g = gamma[0];
    const float* res = (o == 0 ? x : y) + (size_t)bc * HW;
    const float* tH = g_tH[o];
    const float* tW = g_tW[o];
    int tx = threadIdx.x, ty = threadIdx.y;

#pragma unroll
    for (int r = 0; r < 32; r += 8) {
        int w = w0 + ty + r;
        tile[ty + r][tx] = tH[(((size_t)b * LL + w) * Cc + c) * LL + h0 + tx];
    }
    __syncthreads();
    float* op = out + (size_t)o * BCHW + (size_t)bc * HW;
#pragma unroll
    for (int r = 0; r < 32; r += 8) {
        int h = h0 + ty + r;
        size_t ro = (size_t)h * LL + w0 + tx;
        float tw = tW[(((size_t)b * LL + h) * Cc + c) * LL + w0 + tx];
        op[ro] = g * (tile[tx][ty + r] + tw) + res[ro];
    }
}

// ---------------------------------------------------------------------------
extern "C" void kernel_launch(void* const* d_in, const int* in_sizes, int n_in,
                              void* d_out, int out_size)
{
    const float* x     = (const float*)d_in[0];
    const float* y     = (const float*)d_in[1];
    const float* Wq    = (const float*)d_in[2];
    const float* bq    = (const float*)d_in[3];
    const float* Wk    = (const float*)d_in[4];
    const float* bk    = (const float*)d_in[5];
    const float* Wv    = (const float*)d_in[6];
    const float* bv    = (const float*)d_in[7];
    const float* gamma = (const float*)d_in[8];
    float* out = (float*)d_out;
    (void)in_sizes; (void)n_in; (void)out_size;

    float *qk, *qkT, *v, *vT, *eH, *eW, *tH, *tW, *Wqk, *bqk;
    cudaGetSymbolAddress((void**)&qk,  g_qk);
    cudaGetSymbolAddress((void**)&qkT, g_qkT);
    cudaGetSymbolAddress((void**)&v,   g_v);
    cudaGetSymbolAddress((void**)&vT,  g_vT);
    cudaGetSymbolAddress((void**)&eH,  g_eH);
    cudaGetSymbolAddress((void**)&eW,  g_eW);
    cudaGetSymbolAddress((void**)&tH,  g_tH);
    cudaGetSymbolAddress((void**)&tW,  g_tW);
    cudaGetSymbolAddress((void**)&Wqk, g_Wqk);
    cudaGetSymbolAddress((void**)&bqk, g_bqk);

    const int ESM = 2 * 64 * 97 * 4;                // 49664
    const int ASM = (96 * 136 + 96 * 104) * 4;      // 92160
    cudaFuncSetAttribute(energy_kernel,     cudaFuncAttributeMaxDynamicSharedMemorySize, ESM);
    cudaFuncSetAttribute(apply_tf32_kernel, cudaFuncAttributeMaxDynamicSharedMemorySize, ASM);

    float* qk0  = qk;          float* qk1  = qk  + BQKHW;
    float* qkT0 = qkT;         float* qkT1 = qkT + BQKHW;
    float* v0 = v;             float* v1 = v  + BCHW;
    float* vT0 = vT;           float* vT1 = vT + BCHW;
    float* eH0 = eH;           float* eH1 = eH + ELN;
    float* eW0 = eW;           float* eW1 = eW + ELN;
    float* tH0 = tH;           float* tH1 = tH + BCHW;
    float* tW0 = tW;           float* tW1 = tW + BCHW;

    // 0) stack Wq||Wk
    concat_w_kernel<<<128, 256>>>(Wq, bq, Wk, bk);

    // 1) projections (tf32 tensor cores)
    proj_tf32_kernel<<<dim3(72, 1, Bz), 256>>>(x, Wqk, bqk, qk0, 128);
    proj_tf32_kernel<<<dim3(72, 1, Bz), 256>>>(y, Wqk, bqk, qk1, 128);
    proj_tf32_kernel<<<dim3(72, 4, Bz), 256>>>(x, Wv, bv, v0, Cc);
    proj_tf32_kernel<<<dim3(72, 4, Bz), 256>>>(y, Wv, bv, v1, Cc);

    // 2) transposes (H<->W)
    dim3 tb(32, 8);
    transpose_kernel<<<dim3(3, 3, Bz * 128), tb>>>(qk0, qkT0);
    transpose_kernel<<<dim3(3, 3, Bz * 128), tb>>>(qk1, qkT1);
    transpose_kernel<<<dim3(3, 3, Bz * Cc),  tb>>>(v0, vT0);
    transpose_kernel<<<dim3(3, 3, Bz * Cc),  tb>>>(v1, vT1);

    // 3) energies (dir0: q from x, keys from y; dir1: q from y, keys from x)
    const size_t QKB = (size_t)128 * HW;
    energy_kernel<<<Bz * LL, 256, ESM>>>(qkT0, qkT1 + 64 * HW, eH0, 1, QKB);
    energy_kernel<<<Bz * LL, 256, ESM>>>(qkT1, qkT0 + 64 * HW, eH1, 1, QKB);
    energy_kernel<<<Bz * LL, 256, ESM>>>(qk0,  qk1  + 64 * HW, eW0, 0, QKB);
    energy_kernel<<<Bz * LL, 256, ESM>>>(qk1,  qk0  + 64 * HW, eW1, 0, QKB);

    // 4) joint softmax (in place -> attention)
    softmax_kernel<<<dim3(9216, 2), 256>>>();

    // 5) applies: out1 = vx with att_yx(dir1); out2 = vy with att_xy(dir0)
    apply_tf32_kernel<<<dim3(4, Bz * LL), 256, ASM>>>(vT0, eH1, tH0);
    apply_tf32_kernel<<<dim3(4, Bz * LL), 256, ASM>>>(v0,  eW1, tW0);
    apply_tf32_kernel<<<dim3(4, Bz * LL), 256, ASM>>>(vT1, eH0, tH1);
    apply_tf32_kernel<<<dim3(4, Bz * LL), 256, ASM>>>(v1,  eW0, tW1);

    // 6) combine + residual
    final_kernel<<<dim3(3, 3, 2 * Bz * Cc), tb>>>(x, y, gamma, out);
}

// round 4
// speedup vs baseline: 3.3553x; 1.7298x over previous
#include <cuda_runtime.h>
#include <cuda_fp16.h>
#include <math.h>
#include <stdint.h>

// Problem constants
#define Bz   8
#define Cc   512
#define CQq  64
#define LL   96           // H == W == 96
#define HW   9216         // 96*96
#define BCHW 37748736     // 8*512*9216
#define BQKHW 9437184     // 8*128*9216 (stacked q||k)
#define ELN  7077888      // 8*96*96*96

// ---------------- scratch (device globals; allocation-free rule) ------------
__device__ __half g_qk [2][BQKHW];  // [B][128][H][W]: ch 0..63 = q, 64..127 = k
__device__ __half g_qkT[2][BQKHW];  // [B][128][W][H]
__device__ __half g_v  [2][BCHW];   // [B][C][H][W]
__device__ __half g_vT [2][BCHW];   // [B][C][W][H]
__device__ float  g_eH [2][ELN];    // energies [B][W][H][Hk] (fp32 logits)
__device__ float  g_eW [2][ELN];    // [B][H][W][Wk]
__device__ __half g_aH [2][ELN];    // softmaxed attention, fp16
__device__ __half g_aW [2][ELN];
__device__ __half g_tH [2][BCHW];   // applyH out  [B][W][C][H]
__device__ __half g_tW [2][BCHW];   // applyW out  [B][H][C][W]
__device__ float  g_Wqk[128 * 512];
__device__ float  g_bqk[128];

// ---------------- helpers ----------------------------------------------------
__device__ __forceinline__ uint32_t pack2(float lo, float hi)
{
    __half2 h = __floats2half2_rn(lo, hi);
    return *reinterpret_cast<uint32_t*>(&h);
}

__device__ __forceinline__ void mma_f16(float& c0, float& c1, float& c2, float& c3,
                                        uint32_t a0, uint32_t a1, uint32_t a2, uint32_t a3,
                                        uint32_t b0, uint32_t b1)
{
    asm volatile(
        "mma.sync.aligned.m16n8k16.row.col.f32.f16.f16.f32 "
        "{%0,%1,%2,%3}, {%4,%5,%6,%7}, {%8,%9}, {%0,%1,%2,%3};"
        : "+f"(c0), "+f"(c1), "+f"(c2), "+f"(c3)
        : "r"(a0), "r"(a1), "r"(a2), "r"(a3), "r"(b0), "r"(b1));
}

// ---------------- stack Wq||Wk -----------------------------------------------
__global__ void concat_w_kernel(const float* __restrict__ Wq, const float* __restrict__ bq,
                                const float* __restrict__ Wk, const float* __restrict__ bk)
{
    int t = blockIdx.x * blockDim.x + threadIdx.x;
    const int n = 64 * 512;
    if (t < n) { g_Wqk[t] = Wq[t]; g_Wqk[n + t] = Wk[t]; }
    if (t < 64) { g_bqk[t] = bq[t]; g_bqk[64 + t] = bk[t]; }
}

// ---------------- 1x1 conv GEMM via fp16 tensor cores -------------------------
// out[b,m,n] = sum_k W[m,k] in[b,k,n] + bias[m]   (out is fp16)
// 128x128 block tile, K in steps of 32; 8 warps = 2(m) x 4(n), warp 64x32.
__global__ __launch_bounds__(256)
void proj_f16_kernel(const float* __restrict__ in, const float* __restrict__ Wm,
                     const float* __restrict__ bias, __half* __restrict__ out, int Cout)
{
    __shared__ uint32_t As_w[128 * 20];   // [m][k2], k2 0..15, stride 20
    __shared__ uint32_t Bs_w[16 * 136];   // [k2][n], stride 136

    int b  = blockIdx.z;
    int bm = blockIdx.y * 128;
    int bn = blockIdx.x * 128;
    int t  = threadIdx.x;
    int warp = t >> 5, lane = t & 31;
    int g = lane >> 2, tg = lane & 3;
    int mw = (warp >> 2) * 64;
    int nw = (warp & 3) * 32;

    const float* inb = in + (size_t)b * Cc * HW;

    float acc[4][4][4];
#pragma unroll
    for (int i = 0; i < 4; i++)
#pragma unroll
        for (int j = 0; j < 4; j++)
#pragma unroll
            for (int r = 0; r < 4; r++) acc[i][j][r] = 0.f;

    for (int k0 = 0; k0 < Cc; k0 += 32) {
        // A: W[bm+m][k0..k0+31] fp32 -> As_w[m][k2] (half2 per word)
#pragma unroll
        for (int r = 0; r < 4; r++) {
            int i = t + 256 * r;
            int m = i >> 3, kq = (i & 7) * 4;
            float4 w4 = *(const float4*)&Wm[(size_t)(bm + m) * Cc + k0 + kq];
            uint2 u;
            u.x = pack2(w4.x, w4.y);
            u.y = pack2(w4.z, w4.w);
            *(uint2*)&As_w[m * 20 + (kq >> 1)] = u;
        }
        // B: rows 2k2,2k2+1 of in -> Bs_w[k2][n] half2(lo,hi)
#pragma unroll
        for (int r = 0; r < 2; r++) {
            int u = t + 256 * r;
            int k2 = u >> 5, n4 = (u & 31) * 4;
            const float* r0 = &inb[(size_t)(k0 + 2 * k2) * HW + bn + n4];
            float4 lo = *(const float4*)r0;
            float4 hi = *(const float4*)(r0 + HW);
            uint4 w;
            w.x = pack2(lo.x, hi.x); w.y = pack2(lo.y, hi.y);
            w.z = pack2(lo.z, hi.z); w.w = pack2(lo.w, hi.w);
            *(uint4*)&Bs_w[k2 * 136 + n4] = w;
        }
        __syncthreads();
#pragma unroll
        for (int kk = 0; kk < 16; kk += 8) {
            uint32_t a[4][4], bb[4][2];
#pragma unroll
            for (int mt = 0; mt < 4; mt++) {
                int m0 = mw + mt * 16;
                a[mt][0] = As_w[(m0 + g    ) * 20 + kk + tg];
                a[mt][1] = As_w[(m0 + g + 8) * 20 + kk + tg];
                a[mt][2] = As_w[(m0 + g    ) * 20 + kk + tg + 4];
                a[mt][3] = As_w[(m0 + g + 8) * 20 + kk + tg + 4];
            }
#pragma unroll
            for (int nt = 0; nt < 4; nt++) {
                int n0 = nw + nt * 8;
                bb[nt][0] = Bs_w[(kk + tg    ) * 136 + n0 + g];
                bb[nt][1] = Bs_w[(kk + tg + 4) * 136 + n0 + g];
            }
#pragma unroll
            for (int mt = 0; mt < 4; mt++)
#pragma unroll
                for (int nt = 0; nt < 4; nt++)
                    mma_f16(acc[mt][nt][0], acc[mt][nt][1], acc[mt][nt][2], acc[mt][nt][3],
                            a[mt][0], a[mt][1], a[mt][2], a[mt][3],
                            bb[nt][0], bb[nt][1]);
        }
        __syncthreads();
    }
    // epilogue: c0,c1 = (row g, col 2tg,2tg+1); c2,c3 = (row g+8, ...)
#pragma unroll
    for (int mt = 0; mt < 4; mt++) {
        int m0g = bm + mw + mt * 16 + g;
        float bi0 = bias[m0g];
        float bi1 = bias[m0g + 8];
        __half* op0 = out + (size_t)b * Cout * HW + (size_t)m0g * HW + bn;
        __half* op1 = op0 + (size_t)8 * HW;
#pragma unroll
        for (int nt = 0; nt < 4; nt++) {
            int col = nw + nt * 8 + 2 * tg;
            *(__half2*)&op0[col] = __floats2half2_rn(acc[mt][nt][0] + bi0, acc[mt][nt][1] + bi0);
            *(__half2*)&op1[col] = __floats2half2_rn(acc[mt][nt][2] + bi1, acc[mt][nt][3] + bi1);
        }
    }
}

// ---------------- plane transpose (fp16): [N][H][W] -> [N][W][H] --------------
__global__ void transpose16_kernel(const __half* __restrict__ in, __half* __restrict__ out)
{
    __shared__ __half tile[32][34];
    int n = blockIdx.z;
    int h0 = blockIdx.y * 32, w0 = blockIdx.x * 32;
    const __half* ip = in  + (size_t)n * HW;
    __half*       op = out + (size_t)n * HW;
    int tx = threadIdx.x, ty = threadIdx.y;   // 32 x 8
#pragma unroll
    for (int r = 0; r < 32; r += 8)
        tile[ty + r][tx] = ip[(size_t)(h0 + ty + r) * LL + w0 + tx];
    __syncthreads();
#pragma unroll
    for (int r = 0; r < 32; r += 8)
        op[(size_t)(w0 + ty + r) * LL + h0 + tx] = tile[tx][ty + r];
}

// ---------------- energy: per (b,line) S[i,j] = sum_c Q[c,i] K[c,j] -----------
// Q,K are fp16; accumulate fp32; E fp32 logits
__global__ void energy_kernel(const __half* __restrict__ Q, const __half* __restrict__ K,
                              float* __restrict__ E, int maskDiag, size_t bstride)
{
    extern __shared__ float sm[];
    float* Qs = sm;             // [64][97]
    float* Ks = sm + 64 * 97;
    int bl = blockIdx.x;
    int b = bl / LL, line = bl % LL;
    size_t base = (size_t)b * bstride + (size_t)line * LL;
    int t = threadIdx.x;
    for (int idx = t; idx < 64 * 48; idx += 256) {
        int c = idx / 48, i2 = idx % 48;
        __half2 q2 = *(const __half2*)(Q + base + (size_t)c * HW + 2 * i2);
        __half2 k2 = *(const __half2*)(K + base + (size_t)c * HW + 2 * i2);
        Qs[c * 97 + 2 * i2    ] = __low2float(q2);
        Qs[c * 97 + 2 * i2 + 1] = __high2float(q2);
        Ks[c * 97 + 2 * i2    ] = __low2float(k2);
        Ks[c * 97 + 2 * i2 + 1] = __high2float(k2);
    }
    __syncthreads();
    int tx = t & 15, ty = t >> 4;
    float acc[6][6];
#pragma unroll
    for (int a = 0; a < 6; a++)
#pragma unroll
        for (int b2 = 0; b2 < 6; b2++) acc[a][b2] = 0.f;

    for (int c = 0; c < 64; c++) {
        float qv[6], kv[6];
#pragma unroll
        for (int a = 0; a < 6; a++)  qv[a]  = Qs[c * 97 + ty + 16 * a];
#pragma unroll
        for (int b2 = 0; b2 < 6; b2++) kv[b2] = Ks[c * 97 + tx + 16 * b2];
#pragma unroll
        for (int a = 0; a < 6; a++)
#pragma unroll
            for (int b2 = 0; b2 < 6; b2++) acc[a][b2] += qv[a] * kv[b2];
    }
    float* Eb = E + (size_t)bl * LL * LL;
#pragma unroll
    for (int a = 0; a < 6; a++) {
        int i = ty + 16 * a;
#pragma unroll
        for (int b2 = 0; b2 < 6; b2++) {
            int j = tx + 16 * b2;
            Eb[(size_t)i * LL + j] = (maskDiag && i == j) ? -1e30f : acc[a][b2];
        }
    }
}

// ---------------- joint softmax; fp32 logits in, fp16 attention out ----------
__global__ void softmax_kernel()
{
    int dir  = blockIdx.y;
    int warp = (blockIdx.x * blockDim.x + threadIdx.x) >> 5;
    int lane = threadIdx.x & 31;
    int b  = warp / HW;
    int hw = warp % HW;
    int h = hw / LL, w = hw % LL;
    size_t offH = (((size_t)b * LL + w) * LL + h) * LL;
    size_t offW = (((size_t)b * LL + h) * LL + w) * LL;
    const float* rH = &g_eH[dir][offH];
    const float* rW = &g_eW[dir][offW];
    __half* oH = &g_aH[dir][offH];
    __half* oW = &g_aW[dir][offW];
    float v[6];
#pragma unroll
    for (int i = 0; i < 3; i++) v[i]     = rH[lane + 32 * i];
#pragma unroll
    for (int i = 0; i < 3; i++) v[3 + i] = rW[lane + 32 * i];
    float m = v[0];
#pragma unroll
    for (int i = 1; i < 6; i++) m = fmaxf(m, v[i]);
#pragma unroll
    for (int o = 16; o > 0; o >>= 1) m = fmaxf(m, __shfl_xor_sync(0xffffffffu, m, o));
    float s = 0.f;
#pragma unroll
    for (int i = 0; i < 6; i++) { v[i] = __expf(v[i] - m); s += v[i]; }
#pragma unroll
    for (int o = 16; o > 0; o >>= 1) s += __shfl_xor_sync(0xffffffffu, s, o);
    float inv = 1.f / s;
#pragma unroll
    for (int i = 0; i < 3; i++) oH[lane + 32 * i] = __float2half(v[i]     * inv);
#pragma unroll
    for (int i = 0; i < 3; i++) oW[lane + 32 * i] = __float2half(v[3 + i] * inv);
}

// ---------------- apply via fp16 tensor cores ---------------------------------
// per (b,line): O[c,i] = sum_k V[c,k] A[i,k]   (all fp16, fp32 accum)
// M=128(c tile), N=96(i), K=96 fully smem-resident.
// 8 warps = 2(m) x 4(n), warp tile 64x24.
__global__ __launch_bounds__(256)
void apply_f16_kernel(const __half* __restrict__ Vb, const __half* __restrict__ Ab,
                      __half* __restrict__ Ob)
{
    __shared__ uint32_t Vs [128 * 52];   // [c][k2], k2 0..47, stride 52
    __shared__ uint32_t As2[ 96 * 52];   // [i][k2]
    int ct0 = blockIdx.x * 128;
    int bl  = blockIdx.y;
    int b = bl / LL, line = bl % LL;
    int t = threadIdx.x;
    int warp = t >> 5, lane = t & 31;
    int g = lane >> 2, tg = lane & 3;
    int mw = (warp >> 2) * 64;
    int nw = (warp & 3) * 24;

    // V tile: natural [c][k] fp16 rows -> word copy
    const uint32_t* Vp = (const uint32_t*)(Vb + (((size_t)(b * Cc + ct0)) * LL + line) * LL);
#pragma unroll
    for (int r = 0; r < 6; r++) {
        int idx = t + 256 * r;
        int c = idx / 12, w4 = (idx % 12) * 4;
        *(uint4*)&Vs[c * 52 + w4] = *(const uint4*)&Vp[(size_t)c * (HW / 2) + w4];
    }
    // A tile: natural [i][k] fp16 rows -> word copy
    const uint32_t* Ap = (const uint32_t*)(Ab + (size_t)bl * LL * LL);
    for (int idx = t; idx < 96 * 12; idx += 256) {
        int i = idx / 12, w4 = (idx % 12) * 4;
        *(uint4*)&As2[i * 52 + w4] = *(const uint4*)&Ap[i * 48 + w4];
    }
    __syncthreads();

    float acc[4][3][4];
#pragma unroll
    for (int i = 0; i < 4; i++)
#pragma unroll
        for (int j = 0; j < 3; j++)
#pragma unroll
            for (int r = 0; r < 4; r++) acc[i][j][r] = 0.f;

#pragma unroll
    for (int kk = 0; kk < 48; kk += 8) {
        uint32_t a[4][4], bb[3][2];
#pragma unroll
        for (int mt = 0; mt < 4; mt++) {
            int m0 = mw + mt * 16;
            a[mt][0] = Vs[(m0 + g    ) * 52 + kk + tg];
            a[mt][1] = Vs[(m0 + g + 8) * 52 + kk + tg];
            a[mt][2] = Vs[(m0 + g    ) * 52 + kk + tg + 4];
            a[mt][3] = Vs[(m0 + g + 8) * 52 + kk + tg + 4];
        }
#pragma unroll
        for (int nt = 0; nt < 3; nt++) {
            int n0 = nw + nt * 8;
            bb[nt][0] = As2[(n0 + g) * 52 + kk + tg];
            bb[nt][1] = As2[(n0 + g) * 52 + kk + tg + 4];
        }
#pragma unroll
        for (int mt = 0; mt < 4; mt++)
#pragma unroll
            for (int nt = 0; nt < 3; nt++)
                mma_f16(acc[mt][nt][0], acc[mt][nt][1], acc[mt][nt][2], acc[mt][nt][3],
                        a[mt][0], a[mt][1], a[mt][2], a[mt][3],
                        bb[nt][0], bb[nt][1]);
    }

    __half* Op = Ob + ((size_t)bl * Cc + ct0) * LL;
#pragma unroll
    for (int mt = 0; mt < 4; mt++) {
        int m0g = mw + mt * 16 + g;
        __half* o0 = Op + (size_t)m0g * LL;
        __half* o1 = o0 + (size_t)8 * LL;
#pragma unroll
        for (int nt = 0; nt < 3; nt++) {
            int col = nw + nt * 8 + 2 * tg;
            *(__half2*)&o0[col] = __floats2half2_rn(acc[mt][nt][0], acc[mt][nt][1]);
            *(__half2*)&o1[col] = __floats2half2_rn(acc[mt][nt][2], acc[mt][nt][3]);
        }
    }
}

// ---------------- final: out = gamma*(tH^T + tW) + residual (fp32 out) -------
__global__ void final_kernel(const float* __restrict__ x, const float* __restrict__ y,
                             const float* __restrict__ gamma, float* __restrict__ out)
{
    __shared__ __half tile[32][34];
    int z  = blockIdx.z;
    int o  = z >> 12;           // B*C = 4096
    int bc = z & 4095;
    int b  = bc >> 9;
    int c  = bc & 511;
    int h0 = blockIdx.y * 32, w0 = blockIdx.x * 32;
    float g = gamma[0];
    const float* res = (o == 0 ? x : y) + (size_t)bc * HW;
    const __half* tH = g_tH[o];
    const __half* tW = g_tW[o];
    int tx = threadIdx.x, ty = threadIdx.y;

#pragma unroll
    for (int r = 0; r < 32; r += 8) {
        int w = w0 + ty + r;
        tile[ty + r][tx] = tH[(((size_t)b * LL + w) * Cc + c) * LL + h0 + tx];
    }
    __syncthreads();
    float* op = out + (size_t)o * BCHW + (size_t)bc * HW;
#pragma unroll
    for (int r = 0; r < 32; r += 8) {
        int h = h0 + ty + r;
        size_t ro = (size_t)h * LL + w0 + tx;
        float tw = __half2float(tW[(((size_t)b * LL + h) * Cc + c) * LL + w0 + tx]);
        op[ro] = g * (__half2float(tile[tx][ty + r]) + tw) + res[ro];
    }
}

// ---------------------------------------------------------------------------
extern "C" void kernel_launch(void* const* d_in, const int* in_sizes, int n_in,
                              void* d_out, int out_size)
{
    const float* x     = (const float*)d_in[0];
    const float* y     = (const float*)d_in[1];
    const float* Wq    = (const float*)d_in[2];
    const float* bq    = (const float*)d_in[3];
    const float* Wk    = (const float*)d_in[4];
    const float* bk    = (const float*)d_in[5];
    const float* Wv    = (const float*)d_in[6];
    const float* bv    = (const float*)d_in[7];
    const float* gamma = (const float*)d_in[8];
    float* out = (float*)d_out;
    (void)in_sizes; (void)n_in; (void)out_size;

    __half *qk, *qkT, *v, *vT, *aH, *aW, *tH, *tW;
    float *eH, *eW, *Wqk, *bqk;
    cudaGetSymbolAddress((void**)&qk,  g_qk);
    cudaGetSymbolAddress((void**)&qkT, g_qkT);
    cudaGetSymbolAddress((void**)&v,   g_v);
    cudaGetSymbolAddress((void**)&vT,  g_vT);
    cudaGetSymbolAddress((void**)&eH,  g_eH);
    cudaGetSymbolAddress((void**)&eW,  g_eW);
    cudaGetSymbolAddress((void**)&aH,  g_aH);
    cudaGetSymbolAddress((void**)&aW,  g_aW);
    cudaGetSymbolAddress((void**)&tH,  g_tH);
    cudaGetSymbolAddress((void**)&tW,  g_tW);
    cudaGetSymbolAddress((void**)&Wqk, g_Wqk);
    cudaGetSymbolAddress((void**)&bqk, g_bqk);

    const int ESM = 2 * 64 * 97 * 4;   // 49664
    cudaFuncSetAttribute(energy_kernel, cudaFuncAttributeMaxDynamicSharedMemorySize, ESM);

    __half* qk0  = qk;          __half* qk1  = qk  + BQKHW;
    __half* qkT0 = qkT;         __half* qkT1 = qkT + BQKHW;
    __half* v0 = v;             __half* v1 = v  + BCHW;
    __half* vT0 = vT;           __half* vT1 = vT + BCHW;
    float*  eH0 = eH;           float*  eH1 = eH + ELN;
    float*  eW0 = eW;           float*  eW1 = eW + ELN;
    __half* aH0 = aH;           __half* aH1 = aH + ELN;
    __half* aW0 = aW;           __half* aW1 = aW + ELN;
    __half* tH0 = tH;           __half* tH1 = tH + BCHW;
    __half* tW0 = tW;           __half* tW1 = tW + BCHW;

    // 0) stack Wq||Wk
    concat_w_kernel<<<128, 256>>>(Wq, bq, Wk, bk);

    // 1) projections (fp16 tensor cores, fp16 outputs)
    proj_f16_kernel<<<dim3(72, 1, Bz), 256>>>(x, Wqk, bqk, qk0, 128);
    proj_f16_kernel<<<dim3(72, 1, Bz), 256>>>(y, Wqk, bqk, qk1, 128);
    proj_f16_kernel<<<dim3(72, 4, Bz), 256>>>(x, Wv, bv, v0, Cc);
    proj_f16_kernel<<<dim3(72, 4, Bz), 256>>>(y, Wv, bv, v1, Cc);

    // 2) transposes (H<->W), fp16
    dim3 tb(32, 8);
    transpose16_kernel<<<dim3(3, 3, Bz * 128), tb>>>(qk0, qkT0);
    transpose16_kernel<<<dim3(3, 3, Bz * 128), tb>>>(qk1, qkT1);
    transpose16_kernel<<<dim3(3, 3, Bz * Cc),  tb>>>(v0, vT0);
    transpose16_kernel<<<dim3(3, 3, Bz * Cc),  tb>>>(v1, vT1);

    // 3) energies (dir0: q from x, keys from y; dir1: q from y, keys from x)
    const size_t QKB = (size_t)128 * HW;
    energy_kernel<<<Bz * LL, 256, ESM>>>(qkT0, qkT1 + 64 * HW, eH0, 1, QKB);
    energy_kernel<<<Bz * LL, 256, ESM>>>(qkT1, qkT0 + 64 * HW, eH1, 1, QKB);
    energy_kernel<<<Bz * LL, 256, ESM>>>(qk0,  qk1  + 64 * HW, eW0, 0, QKB);
    energy_kernel<<<Bz * LL, 256, ESM>>>(qk1,  qk0  + 64 * HW, eW1, 0, QKB);

    // 4) joint softmax -> fp16 attention
    softmax_kernel<<<dim3(9216, 2), 256>>>();

    // 5) applies: out1 = vx with att_yx(dir1); out2 = vy with att_xy(dir0)
    apply_f16_kernel<<<dim3(4, Bz * LL), 256>>>(vT0, aH1, tH0);
    apply_f16_kernel<<<dim3(4, Bz * LL), 256>>>(v0,  aW1, tW0);
    apply_f16_kernel<<<dim3(4, Bz * LL), 256>>>(vT1, aH0, tH1);
    apply_f16_kernel<<<dim3(4, Bz * LL), 256>>>(v1,  aW0, tW1);

    // 6) combine + residual
    final_kernel<<<dim3(3, 3, 2 * Bz * Cc), tb>>>(x, y, gamma, out);
}

// round 6
// speedup vs baseline: 3.5848x; 1.0684x over previous
#include <cuda_runtime.h>
#include <cuda_fp16.h>
#include <math.h>
#include <stdint.h>

// Problem constants
#define Bz   8
#define Cc   512
#define CQq  64
#define LL   96           // H == W == 96
#define HW   9216         // 96*96
#define BCHW 37748736     // 8*512*9216
#define BQKHW 9437184     // 8*128*9216 (stacked q||k)
#define ELN  7077888      // 8*96*96*96

// ---------------- scratch (device globals; allocation-free rule) ------------
__device__ __half g_qk [2][BQKHW];  // [B][128][H][W]: ch 0..63 = q, 64..127 = k
__device__ __half g_qkT[2][BQKHW];  // [B][128][W][H]
__device__ __half g_v  [2][BCHW];   // [B][C][H][W]
__device__ __half g_vT [2][BCHW];   // [B][C][W][H]
__device__ float  g_eH [2][ELN];    // energies [B][W][H][Hk] (fp32 logits)
__device__ float  g_eW [2][ELN];    // [B][H][W][Wk]
__device__ __half g_aH [2][ELN];    // softmaxed attention, fp16
__device__ __half g_aW [2][ELN];
__device__ __half g_tH [2][BCHW];   // applyH out  [B][W][C][H]
__device__ __half g_tW [2][BCHW];   // applyW out  [B][H][C][W]
__device__ float  g_Wqk[128 * 512];
__device__ float  g_bqk[128];

// ---------------- helpers ----------------------------------------------------
__device__ __forceinline__ uint32_t pack2(float lo, float hi)
{
    __half2 h = __floats2half2_rn(lo, hi);
    return *reinterpret_cast<uint32_t*>(&h);
}

__device__ __forceinline__ void mma_f16(float& c0, float& c1, float& c2, float& c3,
                                        uint32_t a0, uint32_t a1, uint32_t a2, uint32_t a3,
                                        uint32_t b0, uint32_t b1)
{
    asm volatile(
        "mma.sync.aligned.m16n8k16.row.col.f32.f16.f16.f32 "
        "{%0,%1,%2,%3}, {%4,%5,%6,%7}, {%8,%9}, {%0,%1,%2,%3};"
        : "+f"(c0), "+f"(c1), "+f"(c2), "+f"(c3)
        : "r"(a0), "r"(a1), "r"(a2), "r"(a3), "r"(b0), "r"(b1));
}

__device__ __forceinline__ void ldsm_x4(uint32_t& r0, uint32_t& r1, uint32_t& r2, uint32_t& r3,
                                        uint32_t addr)
{
    asm volatile("ldmatrix.sync.aligned.m8n8.x4.shared.b16 {%0,%1,%2,%3}, [%4];"
                 : "=r"(r0), "=r"(r1), "=r"(r2), "=r"(r3) : "r"(addr));
}
__device__ __forceinline__ void ldsm_x4_t(uint32_t& r0, uint32_t& r1, uint32_t& r2, uint32_t& r3,
                                          uint32_t addr)
{
    asm volatile("ldmatrix.sync.aligned.m8n8.x4.trans.shared.b16 {%0,%1,%2,%3}, [%4];"
                 : "=r"(r0), "=r"(r1), "=r"(r2), "=r"(r3) : "r"(addr));
}
__device__ __forceinline__ void ldsm_x2(uint32_t& r0, uint32_t& r1, uint32_t addr)
{
    asm volatile("ldmatrix.sync.aligned.m8n8.x2.shared.b16 {%0,%1}, [%2];"
                 : "=r"(r0), "=r"(r1) : "r"(addr));
}
__device__ __forceinline__ void ldsm_x2_t(uint32_t& r0, uint32_t& r1, uint32_t addr)
{
    asm volatile("ldmatrix.sync.aligned.m8n8.x2.trans.shared.b16 {%0,%1}, [%2];"
                 : "=r"(r0), "=r"(r1) : "r"(addr));
}
__device__ __forceinline__ uint32_t smem_u32(const void* p)
{
    return (uint32_t)__cvta_generic_to_shared(p);
}

// ---------------- stack Wq||Wk -----------------------------------------------
__global__ void concat_w_kernel(const float* __restrict__ Wq, const float* __restrict__ bq,
                                const float* __restrict__ Wk, const float* __restrict__ bk)
{
    int t = blockIdx.x * blockDim.x + threadIdx.x;
    const int n = 64 * 512;
    if (t < n) { g_Wqk[t] = Wq[t]; g_Wqk[n + t] = Wk[t]; }
    if (t < 64) { g_bqk[t] = bq[t]; g_bqk[64 + t] = bk[t]; }
}

// ---------------- 1x1 conv GEMM via fp16 MMA + ldmatrix + pipelined loads ----
// out[b,m,n] = sum_k W[m,k] in[b,k,n] + bias[m]   (out fp16)
// 128x128 block tile, k-tile 32; 8 warps = 2(m) x 4(n), warp 64x32.
__global__ __launch_bounds__(256)
void proj_f16_kernel(const float* __restrict__ in, const float* __restrict__ Wm,
                     const float* __restrict__ bias, __half* __restrict__ out, int Cout)
{
    __shared__ __align__(16) __half As[128 * 40];   // [m][k] k-tile 32, stride 40
    __shared__ __align__(16) __half Bs[ 32 * 136];  // [k][n] stride 136

    int b  = blockIdx.z;
    int bm = blockIdx.y * 128;
    int bn = blockIdx.x * 128;
    int t  = threadIdx.x;
    int warp = t >> 5, lane = t & 31;
    int g = lane >> 2, tg = lane & 3;
    int mw = (warp >> 2) * 64;
    int nw = (warp & 3) * 32;

    const float* inb = in + (size_t)b * Cc * HW;

    // ldmatrix lane address components
    int aRow = (lane & 7) + ((lane >> 3) & 1) * 8;  // row within m16
    int aK8  = ((lane >> 4) & 1) * 8;               // k half-select
    int bRow = (lane & 7) + ((lane >> 3) & 1) * 8;  // k row within k16 (x2: lanes>=16 unused)
    uint32_t asB = smem_u32(As);
    uint32_t bsB = smem_u32(Bs);

    float acc[4][4][4];
#pragma unroll
    for (int i = 0; i < 4; i++)
#pragma unroll
        for (int j = 0; j < 4; j++)
#pragma unroll
            for (int r = 0; r < 4; r++) acc[i][j][r] = 0.f;

    float4 pa[4], pb[4];
    // prefetch tile k0=0
#pragma unroll
    for (int r = 0; r < 4; r++) {
        int i = t + 256 * r;
        int m = i >> 3, kq = (i & 7) * 4;
        pa[r] = *(const float4*)&Wm[(size_t)(bm + m) * Cc + kq];
        int kb = i >> 5, n4 = (i & 31) * 4;
        pb[r] = *(const float4*)&inb[(size_t)kb * HW + bn + n4];
    }

    for (int k0 = 0; k0 < Cc; k0 += 32) {
        // store prefetched tile to smem (fp32 -> fp16)
#pragma unroll
        for (int r = 0; r < 4; r++) {
            int i = t + 256 * r;
            int m = i >> 3, kq = (i & 7) * 4;
            uint2 ua = make_uint2(pack2(pa[r].x, pa[r].y), pack2(pa[r].z, pa[r].w));
            *(uint2*)&As[m * 40 + kq] = ua;
            int kb = i >> 5, n4 = (i & 31) * 4;
            uint2 ub = make_uint2(pack2(pb[r].x, pb[r].y), pack2(pb[r].z, pb[r].w));
            *(uint2*)&Bs[kb * 136 + n4] = ub;
        }
        __syncthreads();
        // prefetch next tile (overlaps with MMA below)
        if (k0 + 32 < Cc) {
#pragma unroll
            for (int r = 0; r < 4; r++) {
                int i = t + 256 * r;
                int m = i >> 3, kq = (i & 7) * 4;
                pa[r] = *(const float4*)&Wm[(size_t)(bm + m) * Cc + k0 + 32 + kq];
                int kb = i >> 5, n4 = (i & 31) * 4;
                pb[r] = *(const float4*)&inb[(size_t)(k0 + 32 + kb) * HW + bn + n4];
            }
        }
#pragma unroll
        for (int kk = 0; kk < 32; kk += 16) {
            uint32_t a[4][4], bb[4][2];
#pragma unroll
            for (int mt = 0; mt < 4; mt++) {
                uint32_t ad = asB + (uint32_t)(((mw + mt * 16 + aRow) * 40 + kk + aK8) * 2);
                ldsm_x4(a[mt][0], a[mt][1], a[mt][2], a[mt][3], ad);
            }
#pragma unroll
            for (int nt = 0; nt < 4; nt++) {
                uint32_t bd = bsB + (uint32_t)(((kk + bRow) * 136 + nw + nt * 8) * 2);
                ldsm_x2_t(bb[nt][0], bb[nt][1], bd);
            }
#pragma unroll
            for (int mt = 0; mt < 4; mt++)
#pragma unroll
                for (int nt = 0; nt < 4; nt++)
                    mma_f16(acc[mt][nt][0], acc[mt][nt][1], acc[mt][nt][2], acc[mt][nt][3],
                            a[mt][0], a[mt][1], a[mt][2], a[mt][3],
                            bb[nt][0], bb[nt][1]);
        }
        __syncthreads();
    }
    // epilogue
#pragma unroll
    for (int mt = 0; mt < 4; mt++) {
        int m0g = bm + mw + mt * 16 + g;
        float bi0 = bias[m0g];
        float bi1 = bias[m0g + 8];
        __half* op0 = out + (size_t)b * Cout * HW + (size_t)m0g * HW + bn;
        __half* op1 = op0 + (size_t)8 * HW;
#pragma unroll
        for (int nt = 0; nt < 4; nt++) {
            int col = nw + nt * 8 + 2 * tg;
            *(__half2*)&op0[col] = __floats2half2_rn(acc[mt][nt][0] + bi0, acc[mt][nt][1] + bi0);
            *(__half2*)&op1[col] = __floats2half2_rn(acc[mt][nt][2] + bi1, acc[mt][nt][3] + bi1);
        }
    }
}

// ---------------- plane transpose (fp16): [N][H][W] -> [N][W][H] --------------
__global__ void transpose16_kernel(const __half* __restrict__ in, __half* __restrict__ out)
{
    __shared__ __half tile[32][34];
    int n = blockIdx.z;
    int h0 = blockIdx.y * 32, w0 = blockIdx.x * 32;
    const __half* ip = in  + (size_t)n * HW;
    __half*       op = out + (size_t)n * HW;
    int tx = threadIdx.x, ty = threadIdx.y;   // 32 x 8
#pragma unroll
    for (int r = 0; r < 32; r += 8)
        tile[ty + r][tx] = ip[(size_t)(h0 + ty + r) * LL + w0 + tx];
    __syncthreads();
#pragma unroll
    for (int r = 0; r < 32; r += 8)
        op[(size_t)(w0 + ty + r) * LL + h0 + tx] = tile[tx][ty + r];
}

// ---------------- energy via fp16 MMA: S[i,j] = sum_c Q[c,i] K[c,j] -----------
// one block per (b,line); 8 warps = 2(m:48) x 4(n:24); fp32 logits out + mask
__global__ __launch_bounds__(256)
void energy_kernel(const __half* __restrict__ Q, const __half* __restrict__ K,
                   float* __restrict__ E, int maskDiag, size_t bstride)
{
    __shared__ __align__(16) __half Qs[64 * 104];   // [c][i] stride 104
    __shared__ __align__(16) __half Ks[64 * 104];
    int bl = blockIdx.x;
    int b = bl / LL, line = bl % LL;
    const __half* Qp = Q + (size_t)b * bstride + (size_t)line * LL;
    const __half* Kp = K + (size_t)b * bstride + (size_t)line * LL;
    int t = threadIdx.x;
    int warp = t >> 5, lane = t & 31;
    int g = lane >> 2, tg = lane & 3;
    int mw = (warp >> 2) * 48;
    int nw = (warp & 3) * 24;

    for (int idx = t; idx < 64 * 12; idx += 256) {
        int c = idx / 12, j8 = (idx % 12) * 8;
        *(uint4*)&Qs[c * 104 + j8] = *(const uint4*)&Qp[(size_t)c * HW + j8];
        *(uint4*)&Ks[c * 104 + j8] = *(const uint4*)&Kp[(size_t)c * HW + j8];
    }
    __syncthreads();

    uint32_t qsB = smem_u32(Qs);
    uint32_t ksB = smem_u32(Ks);
    // A = Q^T via x4.trans: lanes 0-7:(c,i0) 8-15:(c,i0+8) 16-23:(c+8,i0) 24-31:(c+8,i0+8)
    int aMat = lane >> 3;
    int aC = ((aMat >> 1) & 1) * 8 + (lane & 7);
    int aI = (aMat & 1) * 8;
    // B = K via x2.trans: lanes 0-7: c rows, 8-15: c+8
    int bC = ((lane >> 3) & 1) * 8 + (lane & 7);

    float acc[3][3][4];
#pragma unroll
    for (int i = 0; i < 3; i++)
#pragma unroll
        for (int j = 0; j < 3; j++)
#pragma unroll
            for (int r = 0; r < 4; r++) acc[i][j][r] = 0.f;

#pragma unroll
    for (int kk = 0; kk < 64; kk += 16) {
        uint32_t a[3][4], bb[3][2];
#pragma unroll
        for (int mt = 0; mt < 3; mt++) {
            uint32_t ad = qsB + (uint32_t)(((kk + aC) * 104 + mw + mt * 16 + aI) * 2);
            ldsm_x4_t(a[mt][0], a[mt][1], a[mt][2], a[mt][3], ad);
        }
#pragma unroll
        for (int nt = 0; nt < 3; nt++) {
            uint32_t bd = ksB + (uint32_t)(((kk + bC) * 104 + nw + nt * 8) * 2);
            ldsm_x2_t(bb[nt][0], bb[nt][1], bd);
        }
#pragma unroll
        for (int mt = 0; mt < 3; mt++)
#pragma unroll
            for (int nt = 0; nt < 3; nt++)
                mma_f16(acc[mt][nt][0], acc[mt][nt][1], acc[mt][nt][2], acc[mt][nt][3],
                        a[mt][0], a[mt][1], a[mt][2], a[mt][3],
                        bb[nt][0], bb[nt][1]);
    }

    float* Eb = E + (size_t)bl * LL * LL;
#pragma unroll
    for (int mt = 0; mt < 3; mt++) {
        int i0 = mw + mt * 16 + g;
        int i1 = i0 + 8;
#pragma unroll
        for (int nt = 0; nt < 3; nt++) {
            int j0 = nw + nt * 8 + 2 * tg;
            float v0 = acc[mt][nt][0], v1 = acc[mt][nt][1];
            float v2 = acc[mt][nt][2], v3 = acc[mt][nt][3];
            if (maskDiag) {
                if (i0 == j0)     v0 = -1e30f;
                if (i0 == j0 + 1) v1 = -1e30f;
                if (i1 == j0)     v2 = -1e30f;
                if (i1 == j0 + 1) v3 = -1e30f;
            }
            *(float2*)&Eb[(size_t)i0 * LL + j0] = make_float2(v0, v1);
            *(float2*)&Eb[(size_t)i1 * LL + j0] = make_float2(v2, v3);
        }
    }
}

// ---------------- joint softmax; fp32 logits in, fp16 attention out ----------
__global__ void softmax_kernel()
{
    int dir  = blockIdx.y;
    int warp = (blockIdx.x * blockDim.x + threadIdx.x) >> 5;
    int lane = threadIdx.x & 31;
    int b  = warp / HW;
    int hw = warp % HW;
    int h = hw / LL, w = hw % LL;
    size_t offH = (((size_t)b * LL + w) * LL + h) * LL;
    size_t offW = (((size_t)b * LL + h) * LL + w) * LL;
    const float* rH = &g_eH[dir][offH];
    const float* rW = &g_eW[dir][offW];
    __half* oH = &g_aH[dir][offH];
    __half* oW = &g_aW[dir][offW];
    float v[6];
#pragma unroll
    for (int i = 0; i < 3; i++) v[i]     = rH[lane + 32 * i];
#pragma unroll
    for (int i = 0; i < 3; i++) v[3 + i] = rW[lane + 32 * i];
    float m = v[0];
#pragma unroll
    for (int i = 1; i < 6; i++) m = fmaxf(m, v[i]);
#pragma unroll
    for (int o = 16; o > 0; o >>= 1) m = fmaxf(m, __shfl_xor_sync(0xffffffffu, m, o));
    float s = 0.f;
#pragma unroll
    for (int i = 0; i < 6; i++) { v[i] = __expf(v[i] - m); s += v[i]; }
#pragma unroll
    for (int o = 16; o > 0; o >>= 1) s += __shfl_xor_sync(0xffffffffu, s, o);
    float inv = 1.f / s;
#pragma unroll
    for (int i = 0; i < 3; i++) oH[lane + 32 * i] = __float2half(v[i]     * inv);
#pragma unroll
    for (int i = 0; i < 3; i++) oW[lane + 32 * i] = __float2half(v[3 + i] * inv);
}

// ---------------- apply via fp16 MMA + ldmatrix ------------------------------
// per (b,line): O[c,i] = sum_k V[c,k] A[i,k]  (fp16 in/out, fp32 accum)
// M=128(c), N=96(i), K=96 resident. 8 warps = 2(m) x 4(n), warp 64x24.
// smem stride 104 halves (208 B): row offsets mod 128B cycle conflict-free.
__global__ __launch_bounds__(256)
void apply_f16_kernel(const __half* __restrict__ Vb, const __half* __restrict__ Ab,
                      __half* __restrict__ Ob)
{
    __shared__ __align__(16) __half Vs [128 * 104];   // [c][k] stride 104
    __shared__ __align__(16) __half As2[ 96 * 104];   // [i][k] stride 104
    int ct0 = blockIdx.x * 128;
    int bl  = blockIdx.y;
    int b = bl / LL, line = bl % LL;
    int t = threadIdx.x;
    int warp = t >> 5, lane = t & 31;
    int g = lane >> 2, tg = lane & 3;
    int mw = (warp >> 2) * 64;
    int nw = (warp & 3) * 24;

    // V tile: natural [c][k] rows (16B vectors)
    const __half* Vp = Vb + (((size_t)(b * Cc + ct0)) * LL + line) * LL;
#pragma unroll
    for (int r = 0; r < 6; r++) {
        int idx = t + 256 * r;
        int c = idx / 12, j8 = (idx % 12) * 8;
        *(uint4*)&Vs[c * 104 + j8] = *(const uint4*)&Vp[(size_t)c * HW + j8];
    }
    // A tile: natural [i][k]
    const __half* Ap = Ab + (size_t)bl * LL * LL;
    for (int idx = t; idx < 96 * 12; idx += 256) {
        int i = idx / 12, j8 = (idx % 12) * 8;
        *(uint4*)&As2[i * 104 + j8] = *(const uint4*)&Ap[i * LL + j8];
    }
    __syncthreads();

    uint32_t vsB = smem_u32(Vs);
    uint32_t asB = smem_u32(As2);
    int aRow = (lane & 7) + ((lane >> 3) & 1) * 8;
    int aK8  = ((lane >> 4) & 1) * 8;
    int bRowN = lane & 7;                  // n row within n8
    int bK8  = ((lane >> 3) & 1) * 8;      // k half

    float acc[4][3][4];
#pragma unroll
    for (int i = 0; i < 4; i++)
#pragma unroll
        for (int j = 0; j < 3; j++)
#pragma unroll
            for (int r = 0; r < 4; r++) acc[i][j][r] = 0.f;

#pragma unroll
    for (int kk = 0; kk < 96; kk += 16) {
        uint32_t a[4][4], bb[3][2];
#pragma unroll
        for (int mt = 0; mt < 4; mt++) {
            uint32_t ad = vsB + (uint32_t)(((mw + mt * 16 + aRow) * 104 + kk + aK8) * 2);
            ldsm_x4(a[mt][0], a[mt][1], a[mt][2], a[mt][3], ad);
        }
#pragma unroll
        for (int nt = 0; nt < 3; nt++) {
            uint32_t bd = asB + (uint32_t)(((nw + nt * 8 + bRowN) * 104 + kk + bK8) * 2);
            ldsm_x2(bb[nt][0], bb[nt][1], bd);
        }
#pragma unroll
        for (int mt = 0; mt < 4; mt++)
#pragma unroll
            for (int nt = 0; nt < 3; nt++)
                mma_f16(acc[mt][nt][0], acc[mt][nt][1], acc[mt][nt][2], acc[mt][nt][3],
                        a[mt][0], a[mt][1], a[mt][2], a[mt][3],
                        bb[nt][0], bb[nt][1]);
    }

    __half* Op = Ob + ((size_t)bl * Cc + ct0) * LL;
#pragma unroll
    for (int mt = 0; mt < 4; mt++) {
        int m0g = mw + mt * 16 + g;
        __half* o0 = Op + (size_t)m0g * LL;
        __half* o1 = o0 + (size_t)8 * LL;
#pragma unroll
        for (int nt = 0; nt < 3; nt++) {
            int col = nw + nt * 8 + 2 * tg;
            *(__half2*)&o0[col] = __floats2half2_rn(acc[mt][nt][0], acc[mt][nt][1]);
            *(__half2*)&o1[col] = __floats2half2_rn(acc[mt][nt][2], acc[mt][nt][3]);
        }
    }
}

// ---------------- final: out = gamma*(tH^T + tW) + residual (fp32 out) -------
__global__ void final_kernel(const float* __restrict__ x, const float* __restrict__ y,
                             const float* __restrict__ gamma, float* __restrict__ out)
{
    __shared__ __half tile[32][34];
    int z  = blockIdx.z;
    int o  = z >> 12;           // B*C = 4096
    int bc = z & 4095;
    int b  = bc >> 9;
    int c  = bc & 511;
    int h0 = blockIdx.y * 32, w0 = blockIdx.x * 32;
    float g = gamma[0];
    const float* res = (o == 0 ? x : y) + (size_t)bc * HW;
    const __half* tH = g_tH[o];
    const __half* tW = g_tW[o];
    int tx = threadIdx.x, ty = threadIdx.y;

#pragma unroll
    for (int r = 0; r < 32; r += 8) {
        int w = w0 + ty + r;
        tile[ty + r][tx] = tH[(((size_t)b * LL + w) * Cc + c) * LL + h0 + tx];
    }
    __syncthreads();
    float* op = out + (size_t)o * BCHW + (size_t)bc * HW;
#pragma unroll
    for (int r = 0; r < 32; r += 8) {
        int h = h0 + ty + r;
        size_t ro = (size_t)h * LL + w0 + tx;
        float tw = __half2float(tW[(((size_t)b * LL + h) * Cc + c) * LL + w0 + tx]);
        op[ro] = g * (__half2float(tile[tx][ty + r]) + tw) + res[ro];
    }
}

// ---------------------------------------------------------------------------
extern "C" void kernel_launch(void* const* d_in, const int* in_sizes, int n_in,
                              void* d_out, int out_size)
{
    const float* x     = (const float*)d_in[0];
    const float* y     = (const float*)d_in[1];
    const float* Wq    = (const float*)d_in[2];
    const float* bq    = (const float*)d_in[3];
    const float* Wk    = (const float*)d_in[4];
    const float* bk    = (const float*)d_in[5];
    const float* Wv    = (const float*)d_in[6];
    const float* bv    = (const float*)d_in[7];
    const float* gamma = (const float*)d_in[8];
    float* out = (float*)d_out;
    (void)in_sizes; (void)n_in; (void)out_size;

    __half *qk, *qkT, *v, *vT, *aH, *aW, *tH, *tW;
    float *eH, *eW, *Wqk, *bqk;
    cudaGetSymbolAddress((void**)&qk,  g_qk);
    cudaGetSymbolAddress((void**)&qkT, g_qkT);
    cudaGetSymbolAddress((void**)&v,   g_v);
    cudaGetSymbolAddress((void**)&vT,  g_vT);
    cudaGetSymbolAddress((void**)&eH,  g_eH);
    cudaGetSymbolAddress((void**)&eW,  g_eW);
    cudaGetSymbolAddress((void**)&aH,  g_aH);
    cudaGetSymbolAddress((void**)&aW,  g_aW);
    cudaGetSymbolAddress((void**)&tH,  g_tH);
    cudaGetSymbolAddress((void**)&tW,  g_tW);
    cudaGetSymbolAddress((void**)&Wqk, g_Wqk);
    cudaGetSymbolAddress((void**)&bqk, g_bqk);

    __half* qk0  = qk;          __half* qk1  = qk  + BQKHW;
    __half* qkT0 = qkT;         __half* qkT1 = qkT + BQKHW;
    __half* v0 = v;             __half* v1 = v  + BCHW;
    __half* vT0 = vT;           __half* vT1 = vT + BCHW;
    float*  eH0 = eH;           float*  eH1 = eH + ELN;
    float*  eW0 = eW;           float*  eW1 = eW + ELN;
    __half* aH0 = aH;           __half* aH1 = aH + ELN;
    __half* aW0 = aW;           __half* aW1 = aW + ELN;
    __half* tH0 = tH;           __half* tH1 = tH + BCHW;
    __half* tW0 = tW;           __half* tW1 = tW + BCHW;

    // 0) stack Wq||Wk
    concat_w_kernel<<<128, 256>>>(Wq, bq, Wk, bk);

    // 1) projections (fp16 MMA + ldmatrix, pipelined gmem loads)
    proj_f16_kernel<<<dim3(72, 1, Bz), 256>>>(x, Wqk, bqk, qk0, 128);
    proj_f16_kernel<<<dim3(72, 1, Bz), 256>>>(y, Wqk, bqk, qk1, 128);
    proj_f16_kernel<<<dim3(72, 4, Bz), 256>>>(x, Wv, bv, v0, Cc);
    proj_f16_kernel<<<dim3(72, 4, Bz), 256>>>(y, Wv, bv, v1, Cc);

    // 2) transposes (H<->W), fp16
    dim3 tb(32, 8);
    transpose16_kernel<<<dim3(3, 3, Bz * 128), tb>>>(qk0, qkT0);
    transpose16_kernel<<<dim3(3, 3, Bz * 128), tb>>>(qk1, qkT1);
    transpose16_kernel<<<dim3(3, 3, Bz * Cc),  tb>>>(v0, vT0);
    transpose16_kernel<<<dim3(3, 3, Bz * Cc),  tb>>>(v1, vT1);

    // 3) energies (dir0: q from x, keys from y; dir1: q from y, keys from x)
    const size_t QKB = (size_t)128 * HW;
    energy_kernel<<<Bz * LL, 256>>>(qkT0, qkT1 + 64 * HW, eH0, 1, QKB);
    energy_kernel<<<Bz * LL, 256>>>(qkT1, qkT0 + 64 * HW, eH1, 1, QKB);
    energy_kernel<<<Bz * LL, 256>>>(qk0,  qk1  + 64 * HW, eW0, 0, QKB);
    energy_kernel<<<Bz * LL, 256>>>(qk1,  qk0  + 64 * HW, eW1, 0, QKB);

    // 4) joint softmax -> fp16 attention
    softmax_kernel<<<dim3(9216, 2), 256>>>();

    // 5) applies: out1 = vx with att_yx(dir1); out2 = vy with att_xy(dir0)
    apply_f16_kernel<<<dim3(4, Bz * LL), 256>>>(vT0, aH1, tH0);
    apply_f16_kernel<<<dim3(4, Bz * LL), 256>>>(v0,  aW1, tW0);
    apply_f16_kernel<<<dim3(4, Bz * LL), 256>>>(vT1, aH0, tH1);
    apply_f16_kernel<<<dim3(4, Bz * LL), 256>>>(v1,  aW0, tW1);

    // 6) combine + residual
    final_kernel<<<dim3(3, 3, 2 * Bz * Cc), tb>>>(x, y, gamma, out);
}

// round 7
// speedup vs baseline: 4.0179x; 1.1208x over previous
#include <cuda_runtime.h>
#include <cuda_fp16.h>
#include <math.h>
#include <stdint.h>

// Problem constants
#define Bz   8
#define Cc   512
#define CQq  64
#define LL   96           // H == W == 96
#define HW   9216         // 96*96
#define BCHW 37748736     // 8*512*9216
#define BQKHW 9437184     // 8*128*9216 (stacked q||k)
#define ELN  7077888      // 8*96*96*96

// ---------------- scratch (device globals; allocation-free rule) ------------
__device__ __half g_xh [BCHW];      // fp16 copies of inputs
__device__ __half g_yh [BCHW];
__device__ __half g_qk [2][BQKHW];  // [B][128][H][W]: ch 0..63 = q, 64..127 = k
__device__ __half g_qkT[2][BQKHW];  // [B][128][W][H]
__device__ __half g_v  [2][BCHW];   // [B][C][H][W]
__device__ __half g_vT [2][BCHW];   // [B][C][W][H]
__device__ float  g_eH [2][ELN];    // energies [B][W][H][Hk] (fp32 logits)
__device__ float  g_eW [2][ELN];    // [B][H][W][Wk]
__device__ __half g_aH [2][ELN];    // softmaxed attention, fp16
__device__ __half g_aW [2][ELN];
__device__ __half g_tH [2][BCHW];   // applyH out  [B][W][C][H]
__device__ __half g_tW [2][BCHW];   // applyW out  [B][H][C][W]
__device__ __half g_Wqkh[128 * 512];  // fp16 stacked Wq||Wk
__device__ __half g_Wvh [512 * 512];  // fp16 Wv
__device__ float  g_bqk[128];

// ---------------- helpers ----------------------------------------------------
__device__ __forceinline__ uint32_t pack2(float lo, float hi)
{
    __half2 h = __floats2half2_rn(lo, hi);
    return *reinterpret_cast<uint32_t*>(&h);
}

__device__ __forceinline__ void mma_f16(float& c0, float& c1, float& c2, float& c3,
                                        uint32_t a0, uint32_t a1, uint32_t a2, uint32_t a3,
                                        uint32_t b0, uint32_t b1)
{
    asm volatile(
        "mma.sync.aligned.m16n8k16.row.col.f32.f16.f16.f32 "
        "{%0,%1,%2,%3}, {%4,%5,%6,%7}, {%8,%9}, {%0,%1,%2,%3};"
        : "+f"(c0), "+f"(c1), "+f"(c2), "+f"(c3)
        : "r"(a0), "r"(a1), "r"(a2), "r"(a3), "r"(b0), "r"(b1));
}

__device__ __forceinline__ void ldsm_x4(uint32_t& r0, uint32_t& r1, uint32_t& r2, uint32_t& r3,
                                        uint32_t addr)
{
    asm volatile("ldmatrix.sync.aligned.m8n8.x4.shared.b16 {%0,%1,%2,%3}, [%4];"
                 : "=r"(r0), "=r"(r1), "=r"(r2), "=r"(r3) : "r"(addr));
}
__device__ __forceinline__ void ldsm_x4_t(uint32_t& r0, uint32_t& r1, uint32_t& r2, uint32_t& r3,
                                          uint32_t addr)
{
    asm volatile("ldmatrix.sync.aligned.m8n8.x4.trans.shared.b16 {%0,%1,%2,%3}, [%4];"
                 : "=r"(r0), "=r"(r1), "=r"(r2), "=r"(r3) : "r"(addr));
}
__device__ __forceinline__ void ldsm_x2(uint32_t& r0, uint32_t& r1, uint32_t addr)
{
    asm volatile("ldmatrix.sync.aligned.m8n8.x2.shared.b16 {%0,%1}, [%2];"
                 : "=r"(r0), "=r"(r1) : "r"(addr));
}
__device__ __forceinline__ void ldsm_x2_t(uint32_t& r0, uint32_t& r1, uint32_t addr)
{
    asm volatile("ldmatrix.sync.aligned.m8n8.x2.trans.shared.b16 {%0,%1}, [%2];"
                 : "=r"(r0), "=r"(r1) : "r"(addr));
}
__device__ __forceinline__ uint32_t smem_u32(const void* p)
{
    return (uint32_t)__cvta_generic_to_shared(p);
}
__device__ __forceinline__ void cp16(uint32_t dst, const void* src)
{
    asm volatile("cp.async.cg.shared.global [%0], [%1], 16;" :: "r"(dst), "l"(src));
}
__device__ __forceinline__ void cp_commit() { asm volatile("cp.async.commit_group;"); }
__device__ __forceinline__ void cp_wait0()  { asm volatile("cp.async.wait_group 0;" ::: "memory"); }

// ---------------- fp32 -> fp16 convert ---------------------------------------
__global__ void f2h_kernel(const float* __restrict__ src, __half* __restrict__ dst)
{
    int i = (blockIdx.x * blockDim.x + threadIdx.x) * 8;
    float4 a = *(const float4*)&src[i];
    float4 b = *(const float4*)&src[i + 4];
    uint4 u = make_uint4(pack2(a.x, a.y), pack2(a.z, a.w), pack2(b.x, b.y), pack2(b.z, b.w));
    *(uint4*)&dst[i] = u;
}

// ---------------- weights: stack Wq||Wk (fp16) + Wv (fp16) -------------------
__global__ void weights_kernel(const float* __restrict__ Wq, const float* __restrict__ bq,
                               const float* __restrict__ Wk, const float* __restrict__ bk,
                               const float* __restrict__ Wv)
{
    int t = blockIdx.x * blockDim.x + threadIdx.x;   // 0..262143
    const int n = 64 * 512;
    g_Wvh[t] = __float2half(Wv[t]);
    if (t < n) {
        g_Wqkh[t]     = __float2half(Wq[t]);
        g_Wqkh[n + t] = __float2half(Wk[t]);
    }
    if (t < 64) { g_bqk[t] = bq[t]; g_bqk[64 + t] = bk[t]; }
}

// ---------------- 1x1 conv GEMM: fp16 MMA + ldmatrix + cp.async 2-stage ------
// out[b,m,n] = sum_k W[m,k] in[b,k,n] + bias[m]   (in/W/out fp16, fp32 accum)
// 128x128 block tile, k-tile 32; 8 warps = 2(m) x 4(n), warp 64x32.
#define A_STG (128 * 40)
#define B_STG (32 * 136)
__global__ __launch_bounds__(256)
void proj_f16_kernel(const __half* __restrict__ in, const __half* __restrict__ Wm,
                     const float* __restrict__ bias, __half* __restrict__ out, int Cout)
{
    __shared__ __align__(16) __half As[2][A_STG];   // [m][k] stride 40
    __shared__ __align__(16) __half Bs[2][B_STG];   // [k][n] stride 136

    int b  = blockIdx.z;
    int bm = blockIdx.y * 128;
    int bn = blockIdx.x * 128;
    int t  = threadIdx.x;
    int warp = t >> 5, lane = t & 31;
    int g = lane >> 2, tg = lane & 3;
    int mw = (warp >> 2) * 64;
    int nw = (warp & 3) * 32;

    const __half* inb = in + (size_t)b * Cc * HW;

    int aRow = (lane & 7) + ((lane >> 3) & 1) * 8;
    int aK8  = ((lane >> 4) & 1) * 8;
    int bRow = (lane & 7) + ((lane >> 3) & 1) * 8;
    uint32_t asB = smem_u32(&As[0][0]);
    uint32_t bsB = smem_u32(&Bs[0][0]);

    // cp.async indices (2 chunks each for A and B per thread)
    int am0 = t >> 1,          ac0 = (t & 1) * 2;        // A: 128 rows x 4 chunks
    int bk0 = t >> 3,          bc0 = (t & 7) * 2;        // B: 32 rows x 16 chunks

    float acc[4][4][4];
#pragma unroll
    for (int i = 0; i < 4; i++)
#pragma unroll
        for (int j = 0; j < 4; j++)
#pragma unroll
            for (int r = 0; r < 4; r++) acc[i][j][r] = 0.f;

    // prologue: load stage 0
    {
        cp16(asB + (uint32_t)((am0 * 40 + (ac0 + 0) * 8) * 2), &Wm[(size_t)(bm + am0) * Cc + (ac0 + 0) * 8]);
        cp16(asB + (uint32_t)((am0 * 40 + (ac0 + 1) * 8) * 2), &Wm[(size_t)(bm + am0) * Cc + (ac0 + 1) * 8]);
        cp16(bsB + (uint32_t)((bk0 * 136 + (bc0 + 0) * 8) * 2), &inb[(size_t)bk0 * HW + bn + (bc0 + 0) * 8]);
        cp16(bsB + (uint32_t)((bk0 * 136 + (bc0 + 1) * 8) * 2), &inb[(size_t)bk0 * HW + bn + (bc0 + 1) * 8]);
        cp_commit();
    }

    int buf = 0;
    for (int k0 = 0; k0 < Cc; k0 += 32) {
        cp_wait0();
        __syncthreads();
        if (k0 + 32 < Cc) {
            int s = buf ^ 1;
            uint32_t aD = asB + (uint32_t)(s * A_STG * 2);
            uint32_t bD = bsB + (uint32_t)(s * B_STG * 2);
            cp16(aD + (uint32_t)((am0 * 40 + (ac0 + 0) * 8) * 2), &Wm[(size_t)(bm + am0) * Cc + k0 + 32 + (ac0 + 0) * 8]);
            cp16(aD + (uint32_t)((am0 * 40 + (ac0 + 1) * 8) * 2), &Wm[(size_t)(bm + am0) * Cc + k0 + 32 + (ac0 + 1) * 8]);
            cp16(bD + (uint32_t)((bk0 * 136 + (bc0 + 0) * 8) * 2), &inb[(size_t)(k0 + 32 + bk0) * HW + bn + (bc0 + 0) * 8]);
            cp16(bD + (uint32_t)((bk0 * 136 + (bc0 + 1) * 8) * 2), &inb[(size_t)(k0 + 32 + bk0) * HW + bn + (bc0 + 1) * 8]);
            cp_commit();
        }
        uint32_t aBase = asB + (uint32_t)(buf * A_STG * 2);
        uint32_t bBase = bsB + (uint32_t)(buf * B_STG * 2);
#pragma unroll
        for (int kk = 0; kk < 32; kk += 16) {
            uint32_t a[4][4], bb[4][2];
#pragma unroll
            for (int mt = 0; mt < 4; mt++) {
                uint32_t ad = aBase + (uint32_t)(((mw + mt * 16 + aRow) * 40 + kk + aK8) * 2);
                ldsm_x4(a[mt][0], a[mt][1], a[mt][2], a[mt][3], ad);
            }
#pragma unroll
            for (int nt = 0; nt < 4; nt++) {
                uint32_t bd = bBase + (uint32_t)(((kk + bRow) * 136 + nw + nt * 8) * 2);
                ldsm_x2_t(bb[nt][0], bb[nt][1], bd);
            }
#pragma unroll
            for (int mt = 0; mt < 4; mt++)
#pragma unroll
                for (int nt = 0; nt < 4; nt++)
                    mma_f16(acc[mt][nt][0], acc[mt][nt][1], acc[mt][nt][2], acc[mt][nt][3],
                            a[mt][0], a[mt][1], a[mt][2], a[mt][3],
                            bb[nt][0], bb[nt][1]);
        }
        buf ^= 1;
    }
    // epilogue
#pragma unroll
    for (int mt = 0; mt < 4; mt++) {
        int m0g = bm + mw + mt * 16 + g;
        float bi0 = bias[m0g];
        float bi1 = bias[m0g + 8];
        __half* op0 = out + (size_t)b * Cout * HW + (size_t)m0g * HW + bn;
        __half* op1 = op0 + (size_t)8 * HW;
#pragma unroll
        for (int nt = 0; nt < 4; nt++) {
            int col = nw + nt * 8 + 2 * tg;
            *(__half2*)&op0[col] = __floats2half2_rn(acc[mt][nt][0] + bi0, acc[mt][nt][1] + bi0);
            *(__half2*)&op1[col] = __floats2half2_rn(acc[mt][nt][2] + bi1, acc[mt][nt][3] + bi1);
        }
    }
}

// ---------------- plane transpose (fp16, half2-vectorized) -------------------
// [N][H][W] -> [N][W][H], 32x32 tiles, block (16,16)
__global__ void transpose16_kernel(const __half* __restrict__ in, __half* __restrict__ out)
{
    __shared__ __half2 til[32][17];
    int n = blockIdx.z;
    int h0 = blockIdx.y * 32, w0 = blockIdx.x * 32;
    const __half* ip = in  + (size_t)n * HW;
    __half*       op = out + (size_t)n * HW;
    int tx = threadIdx.x, ty = threadIdx.y;   // 16 x 16
#pragma unroll
    for (int r = 0; r < 32; r += 16)
        til[ty + r][tx] = *(const __half2*)&ip[(size_t)(h0 + ty + r) * LL + w0 + 2 * tx];
    __syncthreads();
#pragma unroll
    for (int r = 0; r < 32; r += 16) {
        int w = ty + r;
        int k = w >> 1, ln = w & 1;
        __half2 A = til[2 * tx][k];
        __half2 B = til[2 * tx + 1][k];
        __half a = ln ? __high2half(A) : __low2half(A);
        __half b = ln ? __high2half(B) : __low2half(B);
        *(__half2*)&op[(size_t)(w0 + w) * LL + h0 + 2 * tx] = __halves2half2(a, b);
    }
}

// ---------------- energy via fp16 MMA: S[i,j] = sum_c Q[c,i] K[c,j] -----------
__global__ __launch_bounds__(256)
void energy_kernel(const __half* __restrict__ Q, const __half* __restrict__ K,
                   float* __restrict__ E, int maskDiag, size_t bstride)
{
    __shared__ __align__(16) __half Qs[64 * 104];   // [c][i] stride 104
    __shared__ __align__(16) __half Ks[64 * 104];
    int bl = blockIdx.x;
    int b = bl / LL, line = bl % LL;
    const __half* Qp = Q + (size_t)b * bstride + (size_t)line * LL;
    const __half* Kp = K + (size_t)b * bstride + (size_t)line * LL;
    int t = threadIdx.x;
    int warp = t >> 5, lane = t & 31;
    int g = lane >> 2, tg = lane & 3;
    int mw = (warp >> 2) * 48;
    int nw = (warp & 3) * 24;

    for (int idx = t; idx < 64 * 12; idx += 256) {
        int c = idx / 12, j8 = (idx % 12) * 8;
        *(uint4*)&Qs[c * 104 + j8] = *(const uint4*)&Qp[(size_t)c * HW + j8];
        *(uint4*)&Ks[c * 104 + j8] = *(const uint4*)&Kp[(size_t)c * HW + j8];
    }
    __syncthreads();

    uint32_t qsB = smem_u32(Qs);
    uint32_t ksB = smem_u32(Ks);
    int aMat = lane >> 3;
    int aC = ((aMat >> 1) & 1) * 8 + (lane & 7);
    int aI = (aMat & 1) * 8;
    int bC = ((lane >> 3) & 1) * 8 + (lane & 7);

    float acc[3][3][4];
#pragma unroll
    for (int i = 0; i < 3; i++)
#pragma unroll
        for (int j = 0; j < 3; j++)
#pragma unroll
            for (int r = 0; r < 4; r++) acc[i][j][r] = 0.f;

#pragma unroll
    for (int kk = 0; kk < 64; kk += 16) {
        uint32_t a[3][4], bb[3][2];
#pragma unroll
        for (int mt = 0; mt < 3; mt++) {
            uint32_t ad = qsB + (uint32_t)(((kk + aC) * 104 + mw + mt * 16 + aI) * 2);
            ldsm_x4_t(a[mt][0], a[mt][1], a[mt][2], a[mt][3], ad);
        }
#pragma unroll
        for (int nt = 0; nt < 3; nt++) {
            uint32_t bd = ksB + (uint32_t)(((kk + bC) * 104 + nw + nt * 8) * 2);
            ldsm_x2_t(bb[nt][0], bb[nt][1], bd);
        }
#pragma unroll
        for (int mt = 0; mt < 3; mt++)
#pragma unroll
            for (int nt = 0; nt < 3; nt++)
                mma_f16(acc[mt][nt][0], acc[mt][nt][1], acc[mt][nt][2], acc[mt][nt][3],
                        a[mt][0], a[mt][1], a[mt][2], a[mt][3],
                        bb[nt][0], bb[nt][1]);
    }

    float* Eb = E + (size_t)bl * LL * LL;
#pragma unroll
    for (int mt = 0; mt < 3; mt++) {
        int i0 = mw + mt * 16 + g;
        int i1 = i0 + 8;
#pragma unroll
        for (int nt = 0; nt < 3; nt++) {
            int j0 = nw + nt * 8 + 2 * tg;
            float v0 = acc[mt][nt][0], v1 = acc[mt][nt][1];
            float v2 = acc[mt][nt][2], v3 = acc[mt][nt][3];
            if (maskDiag) {
                if (i0 == j0)     v0 = -1e30f;
                if (i0 == j0 + 1) v1 = -1e30f;
                if (i1 == j0)     v2 = -1e30f;
                if (i1 == j0 + 1) v3 = -1e30f;
            }
            *(float2*)&Eb[(size_t)i0 * LL + j0] = make_float2(v0, v1);
            *(float2*)&Eb[(size_t)i1 * LL + j0] = make_float2(v2, v3);
        }
    }
}

// ---------------- joint softmax; fp32 logits in, fp16 attention out ----------
__global__ void softmax_kernel()
{
    int dir  = blockIdx.y;
    int warp = (blockIdx.x * blockDim.x + threadIdx.x) >> 5;
    int lane = threadIdx.x & 31;
    int b  = warp / HW;
    int hw = warp % HW;
    int h = hw / LL, w = hw % LL;
    size_t offH = (((size_t)b * LL + w) * LL + h) * LL;
    size_t offW = (((size_t)b * LL + h) * LL + w) * LL;
    const float* rH = &g_eH[dir][offH];
    const float* rW = &g_eW[dir][offW];
    __half* oH = &g_aH[dir][offH];
    __half* oW = &g_aW[dir][offW];
    float v[6];
#pragma unroll
    for (int i = 0; i < 3; i++) v[i]     = rH[lane + 32 * i];
#pragma unroll
    for (int i = 0; i < 3; i++) v[3 + i] = rW[lane + 32 * i];
    float m = v[0];
#pragma unroll
    for (int i = 1; i < 6; i++) m = fmaxf(m, v[i]);
#pragma unroll
    for (int o = 16; o > 0; o >>= 1) m = fmaxf(m, __shfl_xor_sync(0xffffffffu, m, o));
    float s = 0.f;
#pragma unroll
    for (int i = 0; i < 6; i++) { v[i] = __expf(v[i] - m); s += v[i]; }
#pragma unroll
    for (int o = 16; o > 0; o >>= 1) s += __shfl_xor_sync(0xffffffffu, s, o);
    float inv = 1.f / s;
#pragma unroll
    for (int i = 0; i < 3; i++) oH[lane + 32 * i] = __float2half(v[i]     * inv);
#pragma unroll
    for (int i = 0; i < 3; i++) oW[lane + 32 * i] = __float2half(v[3 + i] * inv);
}

// ---------------- apply via fp16 MMA + ldmatrix ------------------------------
// per (b,line): O[c,i] = sum_k V[c,k] A[i,k]  (fp16 in/out, fp32 accum)
__global__ __launch_bounds__(256)
void apply_f16_kernel(const __half* __restrict__ Vb, const __half* __restrict__ Ab,
                      __half* __restrict__ Ob)
{
    __shared__ __align__(16) __half Vs [128 * 104];   // [c][k] stride 104
    __shared__ __align__(16) __half As2[ 96 * 104];   // [i][k] stride 104
    int ct0 = blockIdx.x * 128;
    int bl  = blockIdx.y;
    int b = bl / LL, line = bl % LL;
    int t = threadIdx.x;
    int warp = t >> 5, lane = t & 31;
    int g = lane >> 2, tg = lane & 3;
    int mw = (warp >> 2) * 64;
    int nw = (warp & 3) * 24;

    const __half* Vp = Vb + (((size_t)(b * Cc + ct0)) * LL + line) * LL;
#pragma unroll
    for (int r = 0; r < 6; r++) {
        int idx = t + 256 * r;
        int c = idx / 12, j8 = (idx % 12) * 8;
        *(uint4*)&Vs[c * 104 + j8] = *(const uint4*)&Vp[(size_t)c * HW + j8];
    }
    const __half* Ap = Ab + (size_t)bl * LL * LL;
    for (int idx = t; idx < 96 * 12; idx += 256) {
        int i = idx / 12, j8 = (idx % 12) * 8;
        *(uint4*)&As2[i * 104 + j8] = *(const uint4*)&Ap[i * LL + j8];
    }
    __syncthreads();

    uint32_t vsB = smem_u32(Vs);
    uint32_t asB = smem_u32(As2);
    int aRow = (lane & 7) + ((lane >> 3) & 1) * 8;
    int aK8  = ((lane >> 4) & 1) * 8;
    int bRowN = lane & 7;
    int bK8  = ((lane >> 3) & 1) * 8;

    float acc[4][3][4];
#pragma unroll
    for (int i = 0; i < 4; i++)
#pragma unroll
        for (int j = 0; j < 3; j++)
#pragma unroll
            for (int r = 0; r < 4; r++) acc[i][j][r] = 0.f;

#pragma unroll
    for (int kk = 0; kk < 96; kk += 16) {
        uint32_t a[4][4], bb[3][2];
#pragma unroll
        for (int mt = 0; mt < 4; mt++) {
            uint32_t ad = vsB + (uint32_t)(((mw + mt * 16 + aRow) * 104 + kk + aK8) * 2);
            ldsm_x4(a[mt][0], a[mt][1], a[mt][2], a[mt][3], ad);
        }
#pragma unroll
        for (int nt = 0; nt < 3; nt++) {
            uint32_t bd = asB + (uint32_t)(((nw + nt * 8 + bRowN) * 104 + kk + bK8) * 2);
            ldsm_x2(bb[nt][0], bb[nt][1], bd);
        }
#pragma unroll
        for (int mt = 0; mt < 4; mt++)
#pragma unroll
            for (int nt = 0; nt < 3; nt++)
                mma_f16(acc[mt][nt][0], acc[mt][nt][1], acc[mt][nt][2], acc[mt][nt][3],
                        a[mt][0], a[mt][1], a[mt][2], a[mt][3],
                        bb[nt][0], bb[nt][1]);
    }

    __half* Op = Ob + ((size_t)bl * Cc + ct0) * LL;
#pragma unroll
    for (int mt = 0; mt < 4; mt++) {
        int m0g = mw + mt * 16 + g;
        __half* o0 = Op + (size_t)m0g * LL;
        __half* o1 = o0 + (size_t)8 * LL;
#pragma unroll
        for (int nt = 0; nt < 3; nt++) {
            int col = nw + nt * 8 + 2 * tg;
            *(__half2*)&o0[col] = __floats2half2_rn(acc[mt][nt][0], acc[mt][nt][1]);
            *(__half2*)&o1[col] = __floats2half2_rn(acc[mt][nt][2], acc[mt][nt][3]);
        }
    }
}

// ---------------- final: out = gamma*(tH^T + tW) + residual (half2-vector) ---
// block (16,16); 32x32 tile per block; grid (3,3, 2*B*C)
__global__ void final_kernel(const float* __restrict__ x, const float* __restrict__ y,
                             const float* __restrict__ gamma, float* __restrict__ out)
{
    __shared__ __half2 til[32][17];
    int z  = blockIdx.z;
    int o  = z >> 12;           // B*C = 4096
    int bc = z & 4095;
    int b  = bc >> 9;
    int c  = bc & 511;
    int h0 = blockIdx.y * 32, w0 = blockIdx.x * 32;
    float g = gamma[0];
    const float* res = (o == 0 ? x : y) + (size_t)bc * HW;
    const __half* tH = g_tH[o];
    const __half* tW = g_tW[o];
    int tx = threadIdx.x, ty = threadIdx.y;   // 16 x 16

    // load tH tile: til[w][h2]  (tH: [B][W][C][H], h contiguous)
#pragma unroll
    for (int r = 0; r < 32; r += 16) {
        int w = ty + r;
        til[w][tx] = *(const __half2*)&tH[(((size_t)b * LL + (w0 + w)) * Cc + c) * LL + h0 + 2 * tx];
    }
    __syncthreads();
    float* op = out + (size_t)o * BCHW + (size_t)bc * HW;
#pragma unroll
    for (int r = 0; r < 32; r += 16) {
        int h = ty + r;
        int k = h >> 1, ln = h & 1;
        __half2 A = til[2 * tx][k];
        __half2 B = til[2 * tx + 1][k];
        float a = ln ? __high2float(A) : __low2float(A);
        float bq2 = ln ? __high2float(B) : __low2float(B);
        __half2 tw = *(const __half2*)&tW[(((size_t)b * LL + (h0 + h)) * Cc + c) * LL + w0 + 2 * tx];
        size_t ro = (size_t)(h0 + h) * LL + w0 + 2 * tx;
        float2 rs = *(const float2*)&res[ro];
        float2 ov;
        ov.x = g * (a   + __low2float(tw))  + rs.x;
        ov.y = g * (bq2 + __high2float(tw)) + rs.y;
        *(float2*)&op[ro] = ov;
    }
}

// ---------------------------------------------------------------------------
extern "C" void kernel_launch(void* const* d_in, const int* in_sizes, int n_in,
                              void* d_out, int out_size)
{
    const float* x     = (const float*)d_in[0];
    const float* y     = (const float*)d_in[1];
    const float* Wq    = (const float*)d_in[2];
    const float* bq    = (const float*)d_in[3];
    const float* Wk    = (const float*)d_in[4];
    const float* bk    = (const float*)d_in[5];
    const float* Wv    = (const float*)d_in[6];
    const float* bv    = (const float*)d_in[7];
    const float* gamma = (const float*)d_in[8];
    float* out = (float*)d_out;
    (void)in_sizes; (void)n_in; (void)out_size;

    __half *xh, *yh, *qk, *qkT, *v, *vT, *aH, *aW, *tH, *tW, *Wqkh, *Wvh;
    float *eH, *eW, *bqk;
    cudaGetSymbolAddress((void**)&xh,  g_xh);
    cudaGetSymbolAddress((void**)&yh,  g_yh);
    cudaGetSymbolAddress((void**)&qk,  g_qk);
    cudaGetSymbolAddress((void**)&qkT, g_qkT);
    cudaGetSymbolAddress((void**)&v,   g_v);
    cudaGetSymbolAddress((void**)&vT,  g_vT);
    cudaGetSymbolAddress((void**)&eH,  g_eH);
    cudaGetSymbolAddress((void**)&eW,  g_eW);
    cudaGetSymbolAddress((void**)&aH,  g_aH);
    cudaGetSymbolAddress((void**)&aW,  g_aW);
    cudaGetSymbolAddress((void**)&tH,  g_tH);
    cudaGetSymbolAddress((void**)&tW,  g_tW);
    cudaGetSymbolAddress((void**)&Wqkh, g_Wqkh);
    cudaGetSymbolAddress((void**)&Wvh,  g_Wvh);
    cudaGetSymbolAddress((void**)&bqk,  g_bqk);

    __half* qk0  = qk;          __half* qk1  = qk  + BQKHW;
    __half* qkT0 = qkT;         __half* qkT1 = qkT + BQKHW;
    __half* v0 = v;             __half* v1 = v  + BCHW;
    __half* vT0 = vT;           __half* vT1 = vT + BCHW;
    float*  eH0 = eH;           float*  eH1 = eH + ELN;
    float*  eW0 = eW;           float*  eW1 = eW + ELN;
    __half* aH0 = aH;           __half* aH1 = aH + ELN;
    __half* aW0 = aW;           __half* aW1 = aW + ELN;
    __half* tH0 = tH;           __half* tH1 = tH + BCHW;
    __half* tW0 = tW;           __half* tW1 = tW + BCHW;

    // 0) convert inputs + weights to fp16
    f2h_kernel<<<BCHW / 2048, 256>>>(x, xh);
    f2h_kernel<<<BCHW / 2048, 256>>>(y, yh);
    weights_kernel<<<1024, 256>>>(Wq, bq, Wk, bk, Wv);

    // 1) projections (fp16 MMA + ldmatrix + cp.async double-buffer)
    proj_f16_kernel<<<dim3(72, 1, Bz), 256>>>(xh, Wqkh, bqk, qk0, 128);
    proj_f16_kernel<<<dim3(72, 1, Bz), 256>>>(yh, Wqkh, bqk, qk1, 128);
    proj_f16_kernel<<<dim3(72, 4, Bz), 256>>>(xh, Wvh, bv, v0, Cc);
    proj_f16_kernel<<<dim3(72, 4, Bz), 256>>>(yh, Wvh, bv, v1, Cc);

    // 2) transposes (H<->W), fp16 half2
    dim3 tb(16, 16);
    transpose16_kernel<<<dim3(3, 3, Bz * 128), tb>>>(qk0, qkT0);
    transpose16_kernel<<<dim3(3, 3, Bz * 128), tb>>>(qk1, qkT1);
    transpose16_kernel<<<dim3(3, 3, Bz * Cc),  tb>>>(v0, vT0);
    transpose16_kernel<<<dim3(3, 3, Bz * Cc),  tb>>>(v1, vT1);

    // 3) energies (dir0: q from x, keys from y; dir1: q from y, keys from x)
    const size_t QKB = (size_t)128 * HW;
    energy_kernel<<<Bz * LL, 256>>>(qkT0, qkT1 + 64 * HW, eH0, 1, QKB);
    energy_kernel<<<Bz * LL, 256>>>(qkT1, qkT0 + 64 * HW, eH1, 1, QKB);
    energy_kernel<<<Bz * LL, 256>>>(qk0,  qk1  + 64 * HW, eW0, 0, QKB);
    energy_kernel<<<Bz * LL, 256>>>(qk1,  qk0  + 64 * HW, eW1, 0, QKB);

    // 4) joint softmax -> fp16 attention
    softmax_kernel<<<dim3(9216, 2), 256>>>();

    // 5) applies: out1 = vx with att_yx(dir1); out2 = vy with att_xy(dir0)
    apply_f16_kernel<<<dim3(4, Bz * LL), 256>>>(vT0, aH1, tH0);
    apply_f16_kernel<<<dim3(4, Bz * LL), 256>>>(v0,  aW1, tW0);
    apply_f16_kernel<<<dim3(4, Bz * LL), 256>>>(vT1, aH0, tH1);
    apply_f16_kernel<<<dim3(4, Bz * LL), 256>>>(v1,  aW0, tW1);

    // 6) combine + residual
    final_kernel<<<dim3(3, 3, 2 * Bz * Cc), tb>>>(x, y, gamma, out);
}

// round 8
// speedup vs baseline: 4.3395x; 1.0800x over previous
#include <cuda_runtime.h>
#include <cuda_fp16.h>
#include <math.h>
#include <stdint.h>

// Problem constants
#define Bz   8
#define Cc   512
#define CQq  64
#define LL   96           // H == W == 96
#define HW   9216         // 96*96
#define BCHW 37748736     // 8*512*9216
#define BQKHW 9437184     // 8*128*9216 (stacked q||k)
#define ELN  7077888      // 8*96*96*96

// ---------------- scratch (device globals; allocation-free rule) ------------
__device__ __half g_xh [BCHW];      // fp16 copies of inputs
__device__ __half g_yh [BCHW];
__device__ __half g_qk [2][BQKHW];  // [B][128][H][W]: ch 0..63 = q, 64..127 = k
__device__ __half g_qkT[2][BQKHW];  // [B][128][W][H]
__device__ __half g_v  [2][BCHW];   // [B][C][H][W]
__device__ __half g_vT [2][BCHW];   // [B][C][W][H]
__device__ float  g_eH [2][ELN];    // energies [B][W][H][Hk] (fp32 logits)
__device__ float  g_eW [2][ELN];    // [B][H][W][Wk]
__device__ __half g_aH [2][ELN];    // softmaxed attention, fp16
__device__ __half g_aW [2][ELN];
__device__ __half g_tH [2][BCHW];   // applyH out  [B][W][C][H]
__device__ __half g_tW [2][BCHW];   // applyW out  [B][H][C][W]
__device__ __half g_Wall[640 * 512]; // fp16 stacked Wq||Wk||Wv
__device__ float  g_ball[640];

// ---------------- helpers ----------------------------------------------------
__device__ __forceinline__ uint32_t pack2(float lo, float hi)
{
    __half2 h = __floats2half2_rn(lo, hi);
    return *reinterpret_cast<uint32_t*>(&h);
}

__device__ __forceinline__ void mma_f16(float& c0, float& c1, float& c2, float& c3,
                                        uint32_t a0, uint32_t a1, uint32_t a2, uint32_t a3,
                                        uint32_t b0, uint32_t b1)
{
    asm volatile(
        "mma.sync.aligned.m16n8k16.row.col.f32.f16.f16.f32 "
        "{%0,%1,%2,%3}, {%4,%5,%6,%7}, {%8,%9}, {%0,%1,%2,%3};"
        : "+f"(c0), "+f"(c1), "+f"(c2), "+f"(c3)
        : "r"(a0), "r"(a1), "r"(a2), "r"(a3), "r"(b0), "r"(b1));
}

__device__ __forceinline__ void ldsm_x4(uint32_t& r0, uint32_t& r1, uint32_t& r2, uint32_t& r3,
                                        uint32_t addr)
{
    asm volatile("ldmatrix.sync.aligned.m8n8.x4.shared.b16 {%0,%1,%2,%3}, [%4];"
                 : "=r"(r0), "=r"(r1), "=r"(r2), "=r"(r3) : "r"(addr));
}
__device__ __forceinline__ void ldsm_x4_t(uint32_t& r0, uint32_t& r1, uint32_t& r2, uint32_t& r3,
                                          uint32_t addr)
{
    asm volatile("ldmatrix.sync.aligned.m8n8.x4.trans.shared.b16 {%0,%1,%2,%3}, [%4];"
                 : "=r"(r0), "=r"(r1), "=r"(r2), "=r"(r3) : "r"(addr));
}
__device__ __forceinline__ void ldsm_x2(uint32_t& r0, uint32_t& r1, uint32_t addr)
{
    asm volatile("ldmatrix.sync.aligned.m8n8.x2.shared.b16 {%0,%1}, [%2];"
                 : "=r"(r0), "=r"(r1) : "r"(addr));
}
__device__ __forceinline__ void ldsm_x2_t(uint32_t& r0, uint32_t& r1, uint32_t addr)
{
    asm volatile("ldmatrix.sync.aligned.m8n8.x2.trans.shared.b16 {%0,%1}, [%2];"
                 : "=r"(r0), "=r"(r1) : "r"(addr));
}
__device__ __forceinline__ uint32_t smem_u32(const void* p)
{
    return (uint32_t)__cvta_generic_to_shared(p);
}
__device__ __forceinline__ void cp16(uint32_t dst, const void* src)
{
    asm volatile("cp.async.cg.shared.global [%0], [%1], 16;" :: "r"(dst), "l"(src));
}
__device__ __forceinline__ void cp_commit() { asm volatile("cp.async.commit_group;"); }

// ---------------- fp32 -> fp16 convert ---------------------------------------
__global__ void f2h_kernel(const float* __restrict__ src, __half* __restrict__ dst)
{
    int i = (blockIdx.x * blockDim.x + threadIdx.x) * 8;
    float4 a = *(const float4*)&src[i];
    float4 b = *(const float4*)&src[i + 4];
    uint4 u = make_uint4(pack2(a.x, a.y), pack2(a.z, a.w), pack2(b.x, b.y), pack2(b.z, b.w));
    *(uint4*)&dst[i] = u;
}

// ---------------- weights: stack Wq||Wk||Wv (fp16) + biases -------------------
__global__ void weights_kernel(const float* __restrict__ Wq, const float* __restrict__ bq,
                               const float* __restrict__ Wk, const float* __restrict__ bk,
                               const float* __restrict__ Wv, const float* __restrict__ bv)
{
    int t = blockIdx.x * blockDim.x + threadIdx.x;   // 0..327679
    int m = t >> 9, k = t & 511;
    float w;
    if (m < 64)       w = Wq[m * 512 + k];
    else if (m < 128) w = Wk[(m - 64) * 512 + k];
    else              w = Wv[(m - 128) * 512 + k];
    g_Wall[t] = __float2half(w);
    if (t < 640) {
        float bb;
        if (t < 64)       bb = bq[t];
        else if (t < 128) bb = bk[t - 64];
        else              bb = bv[t - 128];
        g_ball[t] = bb;
    }
}

// ---------------- fused projection GEMM (qk + v), 3-stage cp.async -----------
// out[m,n] = sum_k Wall[m,k] in[b,k,n] + ball[m]; m tile 0 -> qk, 1..4 -> v
// 128x128 block tile, k-tile 32; 8 warps = 2(m) x 4(n), warp 64x32.
#define A_STG 5120                  // halves per stage (128 rows x stride 40)
#define B_STG 4352                  // halves per stage (32 rows x stride 136)
#define STG_H (A_STG + B_STG)       // 9472 halves = 18944 B
#define PROJ_SMEM (3 * STG_H * 2)   // 56832 B
__global__ __launch_bounds__(256)
void proj_f16_kernel(const __half* __restrict__ in, __half* __restrict__ out_qk,
                     __half* __restrict__ out_v)
{
    extern __shared__ __align__(16) __half sm[];

    int b  = blockIdx.z;
    int bm = blockIdx.y * 128;
    int bn = blockIdx.x * 128;
    int t  = threadIdx.x;
    int warp = t >> 5, lane = t & 31;
    int g = lane >> 2, tg = lane & 3;
    int mw = (warp >> 2) * 64;
    int nw = (warp & 3) * 32;

    const __half* inb = in + (size_t)b * Cc * HW;

    int aRow = (lane & 7) + ((lane >> 3) & 1) * 8;
    int aK8  = ((lane >> 4) & 1) * 8;
    int bRow = (lane & 7) + ((lane >> 3) & 1) * 8;

    // cp.async chunk indices (2 chunks each for A and B per thread)
    int am0 = t >> 1, ac0 = (t & 1) * 2;   // A: 128 rows x 4 chunks of 8 halves
    int bk0 = t >> 3, bc0 = (t & 7) * 2;   // B: 32 rows x 16 chunks

    float acc[4][4][4];
#pragma unroll
    for (int i = 0; i < 4; i++)
#pragma unroll
        for (int j = 0; j < 4; j++)
#pragma unroll
            for (int r = 0; r < 4; r++) acc[i][j][r] = 0.f;

    // prologue: stages 0,1
#pragma unroll
    for (int s = 0; s < 2; s++) {
        uint32_t aD = smem_u32(sm + s * STG_H);
        uint32_t bD = aD + A_STG * 2;
        int k0 = s * 32;
        cp16(aD + (uint32_t)((am0 * 40 + (ac0 + 0) * 8) * 2), &g_Wall[(size_t)(bm + am0) * Cc + k0 + (ac0 + 0) * 8]);
        cp16(aD + (uint32_t)((am0 * 40 + (ac0 + 1) * 8) * 2), &g_Wall[(size_t)(bm + am0) * Cc + k0 + (ac0 + 1) * 8]);
        cp16(bD + (uint32_t)((bk0 * 136 + (bc0 + 0) * 8) * 2), &inb[(size_t)(k0 + bk0) * HW + bn + (bc0 + 0) * 8]);
        cp16(bD + (uint32_t)((bk0 * 136 + (bc0 + 1) * 8) * 2), &inb[(size_t)(k0 + bk0) * HW + bn + (bc0 + 1) * 8]);
        cp_commit();
    }

    const int NK = Cc / 32;   // 16
    for (int i = 0; i < NK; i++) {
        asm volatile("cp.async.wait_group 1;" ::: "memory");
        __syncthreads();
        // issue loads for stage i+2 (always commit to keep group counting uniform)
        if (i + 2 < NK) {
            int s = (i + 2) % 3;
            int k0 = (i + 2) * 32;
            uint32_t aD = smem_u32(sm + s * STG_H);
            uint32_t bD = aD + A_STG * 2;
            cp16(aD + (uint32_t)((am0 * 40 + (ac0 + 0) * 8) * 2), &g_Wall[(size_t)(bm + am0) * Cc + k0 + (ac0 + 0) * 8]);
            cp16(aD + (uint32_t)((am0 * 40 + (ac0 + 1) * 8) * 2), &g_Wall[(size_t)(bm + am0) * Cc + k0 + (ac0 + 1) * 8]);
            cp16(bD + (uint32_t)((bk0 * 136 + (bc0 + 0) * 8) * 2), &inb[(size_t)(k0 + bk0) * HW + bn + (bc0 + 0) * 8]);
            cp16(bD + (uint32_t)((bk0 * 136 + (bc0 + 1) * 8) * 2), &inb[(size_t)(k0 + bk0) * HW + bn + (bc0 + 1) * 8]);
        }
        cp_commit();

        uint32_t aBase = smem_u32(sm + (i % 3) * STG_H);
        uint32_t bBase = aBase + A_STG * 2;
#pragma unroll
        for (int kk = 0; kk < 32; kk += 16) {
            uint32_t a[4][4], bb[4][2];
#pragma unroll
            for (int mt = 0; mt < 4; mt++) {
                uint32_t ad = aBase + (uint32_t)(((mw + mt * 16 + aRow) * 40 + kk + aK8) * 2);
                ldsm_x4(a[mt][0], a[mt][1], a[mt][2], a[mt][3], ad);
            }
#pragma unroll
            for (int nt = 0; nt < 4; nt++) {
                uint32_t bd = bBase + (uint32_t)(((kk + bRow) * 136 + nw + nt * 8) * 2);
                ldsm_x2_t(bb[nt][0], bb[nt][1], bd);
            }
#pragma unroll
            for (int mt = 0; mt < 4; mt++)
#pragma unroll
                for (int nt = 0; nt < 4; nt++)
                    mma_f16(acc[mt][nt][0], acc[mt][nt][1], acc[mt][nt][2], acc[mt][nt][3],
                            a[mt][0], a[mt][1], a[mt][2], a[mt][3],
                            bb[nt][0], bb[nt][1]);
        }
    }

    // epilogue: route m tile 0 -> qk buffer, tiles 1..4 -> v buffer
    __half* obase = (bm == 0)
        ? out_qk + (size_t)b * 128 * HW
        : out_v  + (size_t)b * Cc * HW + (size_t)(bm - 128) * HW;
#pragma unroll
    for (int mt = 0; mt < 4; mt++) {
        int mloc = mw + mt * 16 + g;
        float bi0 = g_ball[bm + mloc];
        float bi1 = g_ball[bm + mloc + 8];
        __half* op0 = obase + (size_t)mloc * HW + bn;
        __half* op1 = op0 + (size_t)8 * HW;
#pragma unroll
        for (int nt = 0; nt < 4; nt++) {
            int col = nw + nt * 8 + 2 * tg;
            *(__half2*)&op0[col] = __floats2half2_rn(acc[mt][nt][0] + bi0, acc[mt][nt][1] + bi0);
            *(__half2*)&op1[col] = __floats2half2_rn(acc[mt][nt][2] + bi1, acc[mt][nt][3] + bi1);
        }
    }
}

// ---------------- plane transpose (fp16, half2-vectorized) -------------------
__global__ void transpose16_kernel(const __half* __restrict__ in, __half* __restrict__ out)
{
    __shared__ __half2 til[32][17];
    int n = blockIdx.z;
    int h0 = blockIdx.y * 32, w0 = blockIdx.x * 32;
    const __half* ip = in  + (size_t)n * HW;
    __half*       op = out + (size_t)n * HW;
    int tx = threadIdx.x, ty = threadIdx.y;   // 16 x 16
#pragma unroll
    for (int r = 0; r < 32; r += 16)
        til[ty + r][tx] = *(const __half2*)&ip[(size_t)(h0 + ty + r) * LL + w0 + 2 * tx];
    __syncthreads();
#pragma unroll
    for (int r = 0; r < 32; r += 16) {
        int w = ty + r;
        int k = w >> 1, ln = w & 1;
        __half2 A = til[2 * tx][k];
        __half2 B = til[2 * tx + 1][k];
        __half a = ln ? __high2half(A) : __low2half(A);
        __half b = ln ? __high2half(B) : __low2half(B);
        *(__half2*)&op[(size_t)(w0 + w) * LL + h0 + 2 * tx] = __halves2half2(a, b);
    }
}

// ---------------- energy (merged 4 variants) via fp16 MMA --------------------
// blockIdx.y: 0/1 = H-dir (masked), 2/3 = W-dir; dir = y&1
__global__ __launch_bounds__(256)
void energy_kernel()
{
    __shared__ __align__(16) __half Qs[64 * 104];   // [c][i] stride 104
    __shared__ __align__(16) __half Ks[64 * 104];
    int cfg = blockIdx.y;
    int dir = cfg & 1;
    int isH = (cfg < 2);
    const __half* Q = isH ? g_qkT[dir]     : g_qk[dir];
    const __half* K = isH ? g_qkT[1 - dir] : g_qk[1 - dir];
    K += (size_t)64 * HW;   // keys are channels 64..127
    float* E = isH ? g_eH[dir] : g_eW[dir];
    int maskDiag = isH;

    int bl = blockIdx.x;
    int b = bl / LL, line = bl % LL;
    const size_t QKB = (size_t)128 * HW;
    const __half* Qp = Q + (size_t)b * QKB + (size_t)line * LL;
    const __half* Kp = K + (size_t)b * QKB + (size_t)line * LL;
    int t = threadIdx.x;
    int warp = t >> 5, lane = t & 31;
    int g = lane >> 2, tg = lane & 3;
    int mw = (warp >> 2) * 48;
    int nw = (warp & 3) * 24;

    for (int idx = t; idx < 64 * 12; idx += 256) {
        int c = idx / 12, j8 = (idx % 12) * 8;
        *(uint4*)&Qs[c * 104 + j8] = *(const uint4*)&Qp[(size_t)c * HW + j8];
        *(uint4*)&Ks[c * 104 + j8] = *(const uint4*)&Kp[(size_t)c * HW + j8];
    }
    __syncthreads();

    uint32_t qsB = smem_u32(Qs);
    uint32_t ksB = smem_u32(Ks);
    int aMat = lane >> 3;
    int aC = ((aMat >> 1) & 1) * 8 + (lane & 7);
    int aI = (aMat & 1) * 8;
    int bC = ((lane >> 3) & 1) * 8 + (lane & 7);

    float acc[3][3][4];
#pragma unroll
    for (int i = 0; i < 3; i++)
#pragma unroll
        for (int j = 0; j < 3; j++)
#pragma unroll
            for (int r = 0; r < 4; r++) acc[i][j][r] = 0.f;

#pragma unroll
    for (int kk = 0; kk < 64; kk += 16) {
        uint32_t a[3][4], bb[3][2];
#pragma unroll
        for (int mt = 0; mt < 3; mt++) {
            uint32_t ad = qsB + (uint32_t)(((kk + aC) * 104 + mw + mt * 16 + aI) * 2);
            ldsm_x4_t(a[mt][0], a[mt][1], a[mt][2], a[mt][3], ad);
        }
#pragma unroll
        for (int nt = 0; nt < 3; nt++) {
            uint32_t bd = ksB + (uint32_t)(((kk + bC) * 104 + nw + nt * 8) * 2);
            ldsm_x2_t(bb[nt][0], bb[nt][1], bd);
        }
#pragma unroll
        for (int mt = 0; mt < 3; mt++)
#pragma unroll
            for (int nt = 0; nt < 3; nt++)
                mma_f16(acc[mt][nt][0], acc[mt][nt][1], acc[mt][nt][2], acc[mt][nt][3],
                        a[mt][0], a[mt][1], a[mt][2], a[mt][3],
                        bb[nt][0], bb[nt][1]);
    }

    float* Eb = E + (size_t)bl * LL * LL;
#pragma unroll
    for (int mt = 0; mt < 3; mt++) {
        int i0 = mw + mt * 16 + g;
        int i1 = i0 + 8;
#pragma unroll
        for (int nt = 0; nt < 3; nt++) {
            int j0 = nw + nt * 8 + 2 * tg;
            float v0 = acc[mt][nt][0], v1 = acc[mt][nt][1];
            float v2 = acc[mt][nt][2], v3 = acc[mt][nt][3];
            if (maskDiag) {
                if (i0 == j0)     v0 = -1e30f;
                if (i0 == j0 + 1) v1 = -1e30f;
                if (i1 == j0)     v2 = -1e30f;
                if (i1 == j0 + 1) v3 = -1e30f;
            }
            *(float2*)&Eb[(size_t)i0 * LL + j0] = make_float2(v0, v1);
            *(float2*)&Eb[(size_t)i1 * LL + j0] = make_float2(v2, v3);
        }
    }
}

// ---------------- joint softmax; fp32 logits in, fp16 attention out ----------
__global__ void softmax_kernel()
{
    int dir  = blockIdx.y;
    int warp = (blockIdx.x * blockDim.x + threadIdx.x) >> 5;
    int lane = threadIdx.x & 31;
    int b  = warp / HW;
    int hw = warp % HW;
    int h = hw / LL, w = hw % LL;
    size_t offH = (((size_t)b * LL + w) * LL + h) * LL;
    size_t offW = (((size_t)b * LL + h) * LL + w) * LL;
    const float* rH = &g_eH[dir][offH];
    const float* rW = &g_eW[dir][offW];
    __half* oH = &g_aH[dir][offH];
    __half* oW = &g_aW[dir][offW];
    float v[6];
#pragma unroll
    for (int i = 0; i < 3; i++) v[i]     = rH[lane + 32 * i];
#pragma unroll
    for (int i = 0; i < 3; i++) v[3 + i] = rW[lane + 32 * i];
    float m = v[0];
#pragma unroll
    for (int i = 1; i < 6; i++) m = fmaxf(m, v[i]);
#pragma unroll
    for (int o = 16; o > 0; o >>= 1) m = fmaxf(m, __shfl_xor_sync(0xffffffffu, m, o));
    float s = 0.f;
#pragma unroll
    for (int i = 0; i < 6; i++) { v[i] = __expf(v[i] - m); s += v[i]; }
#pragma unroll
    for (int o = 16; o > 0; o >>= 1) s += __shfl_xor_sync(0xffffffffu, s, o);
    float inv = 1.f / s;
#pragma unroll
    for (int i = 0; i < 3; i++) oH[lane + 32 * i] = __float2half(v[i]     * inv);
#pragma unroll
    for (int i = 0; i < 3; i++) oW[lane + 32 * i] = __float2half(v[3 + i] * inv);
}

// ---------------- apply (merged 4 variants) via fp16 MMA + ldmatrix ----------
// per (b,line): O[c,i] = sum_k V[c,k] A[i,k]; blockIdx.z picks operand set
__global__ __launch_bounds__(256)
void apply_f16_kernel()
{
    __shared__ __align__(16) __half Vs [128 * 104];   // [c][k] stride 104
    __shared__ __align__(16) __half As2[ 96 * 104];   // [i][k] stride 104
    int z = blockIdx.z;
    int half_ = z >> 1;          // which output (0: from x-side v, 1: y-side)
    int isW = z & 1;
    const __half* Vb = isW ? g_v[half_]  : g_vT[half_];
    const __half* Ab = isW ? g_aW[1 - half_] : g_aH[1 - half_];
    __half* Ob = isW ? g_tW[half_] : g_tH[half_];

    int ct0 = blockIdx.x * 128;
    int bl  = blockIdx.y;
    int b = bl / LL, line = bl % LL;
    int t = threadIdx.x;
    int warp = t >> 5, lane = t & 31;
    int g = lane >> 2, tg = lane & 3;
    int mw = (warp >> 2) * 64;
    int nw = (warp & 3) * 24;

    const __half* Vp = Vb + (((size_t)(b * Cc + ct0)) * LL + line) * LL;
#pragma unroll
    for (int r = 0; r < 6; r++) {
        int idx = t + 256 * r;
        int c = idx / 12, j8 = (idx % 12) * 8;
        *(uint4*)&Vs[c * 104 + j8] = *(const uint4*)&Vp[(size_t)c * HW + j8];
    }
    const __half* Ap = Ab + (size_t)bl * LL * LL;
    for (int idx = t; idx < 96 * 12; idx += 256) {
        int i = idx / 12, j8 = (idx % 12) * 8;
        *(uint4*)&As2[i * 104 + j8] = *(const uint4*)&Ap[i * LL + j8];
    }
    __syncthreads();

    uint32_t vsB = smem_u32(Vs);
    uint32_t asB = smem_u32(As2);
    int aRow = (lane & 7) + ((lane >> 3) & 1) * 8;
    int aK8  = ((lane >> 4) & 1) * 8;
    int bRowN = lane & 7;
    int bK8  = ((lane >> 3) & 1) * 8;

    float acc[4][3][4];
#pragma unroll
    for (int i = 0; i < 4; i++)
#pragma unroll
        for (int j = 0; j < 3; j++)
#pragma unroll
            for (int r = 0; r < 4; r++) acc[i][j][r] = 0.f;

#pragma unroll
    for (int kk = 0; kk < 96; kk += 16) {
        uint32_t a[4][4], bb[3][2];
#pragma unroll
        for (int mt = 0; mt < 4; mt++) {
            uint32_t ad = vsB + (uint32_t)(((mw + mt * 16 + aRow) * 104 + kk + aK8) * 2);
            ldsm_x4(a[mt][0], a[mt][1], a[mt][2], a[mt][3], ad);
        }
#pragma unroll
        for (int nt = 0; nt < 3; nt++) {
            uint32_t bd = asB + (uint32_t)(((nw + nt * 8 + bRowN) * 104 + kk + bK8) * 2);
            ldsm_x2(bb[nt][0], bb[nt][1], bd);
        }
#pragma unroll
        for (int mt = 0; mt < 4; mt++)
#pragma unroll
            for (int nt = 0; nt < 3; nt++)
                mma_f16(acc[mt][nt][0], acc[mt][nt][1], acc[mt][nt][2], acc[mt][nt][3],
                        a[mt][0], a[mt][1], a[mt][2], a[mt][3],
                        bb[nt][0], bb[nt][1]);
    }

    __half* Op = Ob + ((size_t)bl * Cc + ct0) * LL;
#pragma unroll
    for (int mt = 0; mt < 4; mt++) {
        int m0g = mw + mt * 16 + g;
        __half* o0 = Op + (size_t)m0g * LL;
        __half* o1 = o0 + (size_t)8 * LL;
#pragma unroll
        for (int nt = 0; nt < 3; nt++) {
            int col = nw + nt * 8 + 2 * tg;
            *(__half2*)&o0[col] = __floats2half2_rn(acc[mt][nt][0], acc[mt][nt][1]);
            *(__half2*)&o1[col] = __floats2half2_rn(acc[mt][nt][2], acc[mt][nt][3]);
        }
    }
}

// ---------------- final: out = gamma*(tH^T + tW) + residual ------------------
__global__ void final_kernel(const float* __restrict__ x, const float* __restrict__ y,
                             const float* __restrict__ gamma, float* __restrict__ out)
{
    __shared__ __half2 til[32][17];
    int z  = blockIdx.z;
    int o  = z >> 12;           // B*C = 4096
    int bc = z & 4095;
    int b  = bc >> 9;
    int c  = bc & 511;
    int h0 = blockIdx.y * 32, w0 = blockIdx.x * 32;
    float g = gamma[0];
    const float* res = (o == 0 ? x : y) + (size_t)bc * HW;
    const __half* tH = g_tH[o];
    const __half* tW = g_tW[o];
    int tx = threadIdx.x, ty = threadIdx.y;   // 16 x 16

#pragma unroll
    for (int r = 0; r < 32; r += 16) {
        int w = ty + r;
        til[w][tx] = *(const __half2*)&tH[(((size_t)b * LL + (w0 + w)) * Cc + c) * LL + h0 + 2 * tx];
    }
    __syncthreads();
    float* op = out + (size_t)o * BCHW + (size_t)bc * HW;
#pragma unroll
    for (int r = 0; r < 32; r += 16) {
        int h = ty + r;
        int k = h >> 1, ln = h & 1;
        __half2 A = til[2 * tx][k];
        __half2 B = til[2 * tx + 1][k];
        float a = ln ? __high2float(A) : __low2float(A);
        float bq2 = ln ? __high2float(B) : __low2float(B);
        __half2 tw = *(const __half2*)&tW[(((size_t)b * LL + (h0 + h)) * Cc + c) * LL + w0 + 2 * tx];
        size_t ro = (size_t)(h0 + h) * LL + w0 + 2 * tx;
        float2 rs = *(const float2*)&res[ro];
        float2 ov;
        ov.x = g * (a   + __low2float(tw))  + rs.x;
        ov.y = g * (bq2 + __high2float(tw)) + rs.y;
        *(float2*)&op[ro] = ov;
    }
}

// ---------------------------------------------------------------------------
extern "C" void kernel_launch(void* const* d_in, const int* in_sizes, int n_in,
                              void* d_out, int out_size)
{
    const float* x     = (const float*)d_in[0];
    const float* y     = (const float*)d_in[1];
    const float* Wq    = (const float*)d_in[2];
    const float* bq    = (const float*)d_in[3];
    const float* Wk    = (const float*)d_in[4];
    const float* bk    = (const float*)d_in[5];
    const float* Wv    = (const float*)d_in[6];
    const float* bv    = (const float*)d_in[7];
    const float* gamma = (const float*)d_in[8];
    float* out = (float*)d_out;
    (void)in_sizes; (void)n_in; (void)out_size;

    __half *xh, *yh, *qk, *qkT, *v, *vT;
    cudaGetSymbolAddress((void**)&xh,  g_xh);
    cudaGetSymbolAddress((void**)&yh,  g_yh);
    cudaGetSymbolAddress((void**)&qk,  g_qk);
    cudaGetSymbolAddress((void**)&qkT, g_qkT);
    cudaGetSymbolAddress((void**)&v,   g_v);
    cudaGetSymbolAddress((void**)&vT,  g_vT);

    cudaFuncSetAttribute(proj_f16_kernel, cudaFuncAttributeMaxDynamicSharedMemorySize, PROJ_SMEM);

    __half* qk0 = qk;   __half* qk1 = qk + BQKHW;
    __half* v0  = v;    __half* v1  = v + BCHW;

    // 0) convert inputs + stack weights to fp16
    f2h_kernel<<<BCHW / 2048, 256>>>(x, xh);
    f2h_kernel<<<BCHW / 2048, 256>>>(y, yh);
    weights_kernel<<<1280, 256>>>(Wq, bq, Wk, bk, Wv, bv);

    // 1) fused projections: one launch per input computes qk and v
    proj_f16_kernel<<<dim3(72, 5, Bz), 256, PROJ_SMEM>>>(xh, qk0, v0);
    proj_f16_kernel<<<dim3(72, 5, Bz), 256, PROJ_SMEM>>>(yh, qk1, v1);

    // 2) transposes (contiguous [2] arrays -> single launch each)
    dim3 tb(16, 16);
    transpose16_kernel<<<dim3(3, 3, 2 * Bz * 128), tb>>>(qk, qkT);
    transpose16_kernel<<<dim3(3, 3, 2 * Bz * Cc),  tb>>>(v, vT);

    // 3) energies (4 variants in one launch)
    energy_kernel<<<dim3(Bz * LL, 4), 256>>>();

    // 4) joint softmax -> fp16 attention
    softmax_kernel<<<dim3(9216, 2), 256>>>();

    // 5) applies (4 variants in one launch)
    apply_f16_kernel<<<dim3(4, Bz * LL, 4), 256>>>();

    // 6) combine + residual
    final_kernel<<<dim3(3, 3, 2 * Bz * Cc), tb>>>(x, y, gamma, out);
}

// round 10
// speedup vs baseline: 4.6580x; 1.0734x over previous
#include <cuda_runtime.h>
#include <cuda_fp16.h>
#include <math.h>
#include <stdint.h>

// Problem constants
#define Bz   8
#define Cc   512
#define CQq  64
#define LL   96           // H == W == 96
#define HW   9216         // 96*96
#define BCHW 37748736     // 8*512*9216
#define BQKHW 9437184     // 8*128*9216 (stacked q||k)
#define ELN  7077888      // 8*96*96*96

// ---------------- scratch (device globals; allocation-free rule) ------------
__device__ __half g_xh [BCHW];      // fp16 copies of inputs [B][C][H][W]
__device__ __half g_yh [BCHW];
__device__ __half g_qk [2][BQKHW];  // [B][128][H][W]: ch 0..63 = q, 64..127 = k
__device__ __half g_qkT[2][BQKHW];  // [B][128][W][H]
__device__ __half g_v  [2][BCHW];   // [B][C][H][W]
__device__ __half g_vT [2][BCHW];   // [B][C][W][H]
__device__ float  g_eH [2][ELN];    // energies [B][W][H][Hk] (fp32 logits)
__device__ float  g_eW [2][ELN];    // [B][H][W][Wk]
__device__ __half g_aH [2][ELN];    // softmaxed attention, fp16
__device__ __half g_aW [2][ELN];
__device__ __half g_tH [2][BCHW];   // applyH out  [B][W][C][H]
__device__ __half g_tW [2][BCHW];   // applyW out  [B][H][C][W]
__device__ __half g_Wall[640 * 512]; // fp16 stacked Wq||Wk||Wv
__device__ float  g_ball[640];

// ---------------- helpers ----------------------------------------------------
__device__ __forceinline__ uint32_t pack2(float lo, float hi)
{
    __half2 h = __floats2half2_rn(lo, hi);
    return *reinterpret_cast<uint32_t*>(&h);
}

__device__ __forceinline__ void mma_f16(float& c0, float& c1, float& c2, float& c3,
                                        uint32_t a0, uint32_t a1, uint32_t a2, uint32_t a3,
                                        uint32_t b0, uint32_t b1)
{
    asm volatile(
        "mma.sync.aligned.m16n8k16.row.col.f32.f16.f16.f32 "
        "{%0,%1,%2,%3}, {%4,%5,%6,%7}, {%8,%9}, {%0,%1,%2,%3};"
        : "+f"(c0), "+f"(c1), "+f"(c2), "+f"(c3)
        : "r"(a0), "r"(a1), "r"(a2), "r"(a3), "r"(b0), "r"(b1));
}

__device__ __forceinline__ void ldsm_x4(uint32_t& r0, uint32_t& r1, uint32_t& r2, uint32_t& r3,
                                        uint32_t addr)
{
    asm volatile("ldmatrix.sync.aligned.m8n8.x4.shared.b16 {%0,%1,%2,%3}, [%4];"
                 : "=r"(r0), "=r"(r1), "=r"(r2), "=r"(r3) : "r"(addr));
}
__device__ __forceinline__ void ldsm_x4_t(uint32_t& r0, uint32_t& r1, uint32_t& r2, uint32_t& r3,
                                          uint32_t addr)
{
    asm volatile("ldmatrix.sync.aligned.m8n8.x4.trans.shared.b16 {%0,%1,%2,%3}, [%4];"
                 : "=r"(r0), "=r"(r1), "=r"(r2), "=r"(r3) : "r"(addr));
}
__device__ __forceinline__ void ldsm_x2(uint32_t& r0, uint32_t& r1, uint32_t addr)
{
    asm volatile("ldmatrix.sync.aligned.m8n8.x2.shared.b16 {%0,%1}, [%2];"
                 : "=r"(r0), "=r"(r1) : "r"(addr));
}
__device__ __forceinline__ void ldsm_x2_t(uint32_t& r0, uint32_t& r1, uint32_t addr)
{
    asm volatile("ldmatrix.sync.aligned.m8n8.x2.trans.shared.b16 {%0,%1}, [%2];"
                 : "=r"(r0), "=r"(r1) : "r"(addr));
}
__device__ __forceinline__ uint32_t smem_u32(const void* p)
{
    return (uint32_t)__cvta_generic_to_shared(p);
}
__device__ __forceinline__ void cp16(uint32_t dst, const void* src)
{
    asm volatile("cp.async.cg.shared.global [%0], [%1], 16;" :: "r"(dst), "l"(src));
}
__device__ __forceinline__ void cp_commit() { asm volatile("cp.async.commit_group;"); }

// ---------------- fp32 -> fp16 convert (both inputs, one launch) --------------
__global__ void f2h_kernel(const float* __restrict__ x, const float* __restrict__ y)
{
    const float* src = blockIdx.y ? y : x;
    __half* dst = blockIdx.y ? g_yh : g_xh;
    int i = (blockIdx.x * blockDim.x + threadIdx.x) * 8;
    float4 a = *(const float4*)&src[i];
    float4 b = *(const float4*)&src[i + 4];
    uint4 u = make_uint4(pack2(a.x, a.y), pack2(a.z, a.w), pack2(b.x, b.y), pack2(b.z, b.w));
    *(uint4*)&dst[i] = u;
}

// ---------------- weights: stack Wq||Wk||Wv (fp16) + biases -------------------
__global__ void weights_kernel(const float* __restrict__ Wq, const float* __restrict__ bq,
                               const float* __restrict__ Wk, const float* __restrict__ bk,
                               const float* __restrict__ Wv, const float* __restrict__ bv)
{
    int t = blockIdx.x * blockDim.x + threadIdx.x;   // 0..327679
    int m = t >> 9, k = t & 511;
    float w;
    if (m < 64)       w = Wq[m * 512 + k];
    else if (m < 128) w = Wk[(m - 64) * 512 + k];
    else              w = Wv[(m - 128) * 512 + k];
    g_Wall[t] = __float2half(w);
    if (t < 640) {
        float bb;
        if (t < 64)       bb = bq[t];
        else if (t < 128) bb = bk[t - 64];
        else              bb = bv[t - 128];
        g_ball[t] = bb;
    }
}

// ---------------- fused projection GEMM (qk + v), k-tile 64, 3-stage ---------
// out[m,n] = sum_k Wall[m,k] in[b,k,n] + ball[m]; m tile 0 -> qk, 1..4 -> v
// 128x128 block tile; 8 warps = 2(m) x 4(n), warp 64x32.
// grid (72, 5, 16): z = input*8 + b
#define A_STG 9216                  // halves per stage: 128 rows x stride 72
#define B_STG 8704                  // halves per stage: 64 rows x stride 136
#define STG_H (A_STG + B_STG)       // 17920 halves = 35840 B
#define PROJ_SMEM (3 * STG_H * 2)   // 107520 B
__global__ __launch_bounds__(256)
void proj_f16_kernel(const __half* __restrict__ xh, const __half* __restrict__ yh)
{
    extern __shared__ __align__(16) __half sm[];

    int inp = blockIdx.z >> 3;
    int b   = blockIdx.z & 7;
    int bm = blockIdx.y * 128;
    int bn = blockIdx.x * 128;
    int t  = threadIdx.x;
    int warp = t >> 5, lane = t & 31;
    int g = lane >> 2, tg = lane & 3;
    int mw = (warp >> 2) * 64;
    int nw = (warp & 3) * 32;

    const __half* in = inp ? yh : xh;
    const __half* inb = in + (size_t)b * Cc * HW;

    int aRow = (lane & 7) + ((lane >> 3) & 1) * 8;
    int aK8  = ((lane >> 4) & 1) * 8;
    int bRow = (lane & 7) + ((lane >> 3) & 1) * 8;

    float acc[4][4][4];
#pragma unroll
    for (int i = 0; i < 4; i++)
#pragma unroll
        for (int j = 0; j < 4; j++)
#pragma unroll
            for (int r = 0; r < 4; r++) acc[i][j][r] = 0.f;

    // loader: k window [c*64, c*64+64) into stage s; 8 cp16 per thread
    auto load_chunk = [&](int c, int s) {
        uint32_t aD = smem_u32(sm + s * STG_H);
        uint32_t bD = aD + A_STG * 2;
        int k0 = c * 64;
#pragma unroll
        for (int r = 0; r < 8; r++) {
            int idx = t + 256 * r;
            if (idx < 1024) {
                int row = idx >> 3, ch = idx & 7;
                cp16(aD + (uint32_t)((row * 72 + ch * 8) * 2),
                     &g_Wall[(size_t)(bm + row) * Cc + k0 + ch * 8]);
            } else {
                int j = idx - 1024;
                int row = j >> 4, ch = j & 15;
                cp16(bD + (uint32_t)((row * 136 + ch * 8) * 2),
                     &inb[(size_t)(k0 + row) * HW + bn + ch * 8]);
            }
        }
    };

    load_chunk(0, 0); cp_commit();
    load_chunk(1, 1); cp_commit();

    const int NK = Cc / 64;   // 8
    for (int i = 0; i < NK; i++) {
        asm volatile("cp.async.wait_group 1;" ::: "memory");
        __syncthreads();
        if (i + 2 < NK) load_chunk(i + 2, (i + 2) % 3);
        cp_commit();

        uint32_t aBase = smem_u32(sm + (i % 3) * STG_H);
        uint32_t bBase = aBase + A_STG * 2;
#pragma unroll
        for (int kk = 0; kk < 64; kk += 16) {
            uint32_t a[4][4], bb[4][2];
#pragma unroll
            for (int mt = 0; mt < 4; mt++) {
                uint32_t ad = aBase + (uint32_t)(((mw + mt * 16 + aRow) * 72 + kk + aK8) * 2);
                ldsm_x4(a[mt][0], a[mt][1], a[mt][2], a[mt][3], ad);
            }
#pragma unroll
            for (int nt = 0; nt < 4; nt++) {
                uint32_t bd = bBase + (uint32_t)(((kk + bRow) * 136 + nw + nt * 8) * 2);
                ldsm_x2_t(bb[nt][0], bb[nt][1], bd);
            }
#pragma unroll
            for (int mt = 0; mt < 4; mt++)
#pragma unroll
                for (int nt = 0; nt < 4; nt++)
                    mma_f16(acc[mt][nt][0], acc[mt][nt][1], acc[mt][nt][2], acc[mt][nt][3],
                            a[mt][0], a[mt][1], a[mt][2], a[mt][3],
                            bb[nt][0], bb[nt][1]);
        }
        __syncthreads();
    }

    // epilogue: route m tile 0 -> qk buffer, tiles 1..4 -> v buffer
    __half* obase = (bm == 0)
        ? g_qk[inp] + (size_t)b * 128 * HW
        : g_v[inp]  + (size_t)b * Cc * HW + (size_t)(bm - 128) * HW;
#pragma unroll
    for (int mt = 0; mt < 4; mt++) {
        int mloc = mw + mt * 16 + g;
        float bi0 = g_ball[bm + mloc];
        float bi1 = g_ball[bm + mloc + 8];
        __half* op0 = obase + (size_t)mloc * HW + bn;
        __half* op1 = op0 + (size_t)8 * HW;
#pragma unroll
        for (int nt = 0; nt < 4; nt++) {
            int col = nw + nt * 8 + 2 * tg;
            *(__half2*)&op0[col] = __floats2half2_rn(acc[mt][nt][0] + bi0, acc[mt][nt][1] + bi0);
            *(__half2*)&op1[col] = __floats2half2_rn(acc[mt][nt][2] + bi1, acc[mt][nt][3] + bi1);
        }
    }
}

// ---------------- plane transpose (fp16, half2-vectorized) -------------------
__global__ void transpose16_kernel(const __half* __restrict__ in, __half* __restrict__ out)
{
    __shared__ __half2 til[32][17];
    int n = blockIdx.z;
    int h0 = blockIdx.y * 32, w0 = blockIdx.x * 32;
    const __half* ip = in  + (size_t)n * HW;
    __half*       op = out + (size_t)n * HW;
    int tx = threadIdx.x, ty = threadIdx.y;   // 16 x 16
#pragma unroll
    for (int r = 0; r < 32; r += 16)
        til[ty + r][tx] = *(const __half2*)&ip[(size_t)(h0 + ty + r) * LL + w0 + 2 * tx];
    __syncthreads();
#pragma unroll
    for (int r = 0; r < 32; r += 16) {
        int w = ty + r;
        int k = w >> 1, ln = w & 1;
        __half2 A = til[2 * tx][k];
        __half2 B = til[2 * tx + 1][k];
        __half a = ln ? __high2half(A) : __low2half(A);
        __half b = ln ? __high2half(B) : __low2half(B);
        *(__half2*)&op[(size_t)(w0 + w) * LL + h0 + 2 * tx] = __halves2half2(a, b);
    }
}

// ---------------- energy (merged 4 variants) via fp16 MMA --------------------
// blockIdx.y: 0/1 = H-dir (masked), 2/3 = W-dir; dir = y&1
__global__ __launch_bounds__(256)
void energy_kernel()
{
    __shared__ __align__(16) __half Qs[64 * 104];   // [c][i] stride 104
    __shared__ __align__(16) __half Ks[64 * 104];
    int cfg = blockIdx.y;
    int dir = cfg & 1;
    int isH = (cfg < 2);
    const __half* Q = isH ? g_qkT[dir]     : g_qk[dir];
    const __half* K = isH ? g_qkT[1 - dir] : g_qk[1 - dir];
    K += (size_t)64 * HW;   // keys are channels 64..127
    float* E = isH ? g_eH[dir] : g_eW[dir];
    int maskDiag = isH;

    int bl = blockIdx.x;
    int b = bl / LL, line = bl % LL;
    const size_t QKB = (size_t)128 * HW;
    const __half* Qp = Q + (size_t)b * QKB + (size_t)line * LL;
    const __half* Kp = K + (size_t)b * QKB + (size_t)line * LL;
    int t = threadIdx.x;
    int warp = t >> 5, lane = t & 31;
    int g = lane >> 2, tg = lane & 3;
    int mw = (warp >> 2) * 48;
    int nw = (warp & 3) * 24;

    for (int idx = t; idx < 64 * 12; idx += 256) {
        int c = idx / 12, j8 = (idx % 12) * 8;
        *(uint4*)&Qs[c * 104 + j8] = *(const uint4*)&Qp[(size_t)c * HW + j8];
        *(uint4*)&Ks[c * 104 + j8] = *(const uint4*)&Kp[(size_t)c * HW + j8];
    }
    __syncthreads();

    uint32_t qsB = smem_u32(Qs);
    uint32_t ksB = smem_u32(Ks);
    int aMat = lane >> 3;
    int aC = ((aMat >> 1) & 1) * 8 + (lane & 7);
    int aI = (aMat & 1) * 8;
    int bC = ((lane >> 3) & 1) * 8 + (lane & 7);

    float acc[3][3][4];
#pragma unroll
    for (int i = 0; i < 3; i++)
#pragma unroll
        for (int j = 0; j < 3; j++)
#pragma unroll
            for (int r = 0; r < 4; r++) acc[i][j][r] = 0.f;

#pragma unroll
    for (int kk = 0; kk < 64; kk += 16) {
        uint32_t a[3][4], bb[3][2];
#pragma unroll
        for (int mt = 0; mt < 3; mt++) {
            uint32_t ad = qsB + (uint32_t)(((kk + aC) * 104 + mw + mt * 16 + aI) * 2);
            ldsm_x4_t(a[mt][0], a[mt][1], a[mt][2], a[mt][3], ad);
        }
#pragma unroll
        for (int nt = 0; nt < 3; nt++) {
            uint32_t bd = ksB + (uint32_t)(((kk + bC) * 104 + nw + nt * 8) * 2);
            ldsm_x2_t(bb[nt][0], bb[nt][1], bd);
        }
#pragma unroll
        for (int mt = 0; mt < 3; mt++)
#pragma unroll
            for (int nt = 0; nt < 3; nt++)
                mma_f16(acc[mt][nt][0], acc[mt][nt][1], acc[mt][nt][2], acc[mt][nt][3],
                        a[mt][0], a[mt][1], a[mt][2], a[mt][3],
                        bb[nt][0], bb[nt][1]);
    }

    float* Eb = E + (size_t)bl * LL * LL;
#pragma unroll
    for (int mt = 0; mt < 3; mt++) {
        int i0 = mw + mt * 16 + g;
        int i1 = i0 + 8;
#pragma unroll
        for (int nt = 0; nt < 3; nt++) {
            int j0 = nw + nt * 8 + 2 * tg;
            float v0 = acc[mt][nt][0], v1 = acc[mt][nt][1];
            float v2 = acc[mt][nt][2], v3 = acc[mt][nt][3];
            if (maskDiag) {
                if (i0 == j0)     v0 = -1e30f;
                if (i0 == j0 + 1) v1 = -1e30f;
                if (i1 == j0)     v2 = -1e30f;
                if (i1 == j0 + 1) v3 = -1e30f;
            }
            *(float2*)&Eb[(size_t)i0 * LL + j0] = make_float2(v0, v1);
            *(float2*)&Eb[(size_t)i1 * LL + j0] = make_float2(v2, v3);
        }
    }
}

// ---------------- joint softmax; fp32 logits in, fp16 attention out ----------
__global__ void softmax_kernel()
{
    int dir  = blockIdx.y;
    int warp = (blockIdx.x * blockDim.x + threadIdx.x) >> 5;
    int lane = threadIdx.x & 31;
    int b  = warp / HW;
    int hw = warp % HW;
    int h = hw / LL, w = hw % LL;
    size_t offH = (((size_t)b * LL + w) * LL + h) * LL;
    size_t offW = (((size_t)b * LL + h) * LL + w) * LL;
    const float* rH = &g_eH[dir][offH];
    const float* rW = &g_eW[dir][offW];
    __half* oH = &g_aH[dir][offH];
    __half* oW = &g_aW[dir][offW];
    float v[6];
#pragma unroll
    for (int i = 0; i < 3; i++) v[i]     = rH[lane + 32 * i];
#pragma unroll
    for (int i = 0; i < 3; i++) v[3 + i] = rW[lane + 32 * i];
    float m = v[0];
#pragma unroll
    for (int i = 1; i < 6; i++) m = fmaxf(m, v[i]);
#pragma unroll
    for (int o = 16; o > 0; o >>= 1) m = fmaxf(m, __shfl_xor_sync(0xffffffffu, m, o));
    float s = 0.f;
#pragma unroll
    for (int i = 0; i < 6; i++) { v[i] = __expf(v[i] - m); s += v[i]; }
#pragma unroll
    for (int o = 16; o > 0; o >>= 1) s += __shfl_xor_sync(0xffffffffu, s, o);
    float inv = 1.f / s;
#pragma unroll
    for (int i = 0; i < 3; i++) oH[lane + 32 * i] = __float2half(v[i]     * inv);
#pragma unroll
    for (int i = 0; i < 3; i++) oW[lane + 32 * i] = __float2half(v[3 + i] * inv);
}

// ---------------- apply (merged 4 variants) via fp16 MMA + ldmatrix ----------
// per (b,line): O[c,i] = sum_k V[c,k] A[i,k]; blockIdx.z picks operand set
__global__ __launch_bounds__(256)
void apply_f16_kernel()
{
    __shared__ __align__(16) __half Vs [128 * 104];   // [c][k] stride 104
    __shared__ __align__(16) __half As2[ 96 * 104];   // [i][k] stride 104
    int z = blockIdx.z;
    int half_ = z >> 1;
    int isW = z & 1;
    const __half* Vb = isW ? g_v[half_]  : g_vT[half_];
    const __half* Ab = isW ? g_aW[1 - half_] : g_aH[1 - half_];
    __half* Ob = isW ? g_tW[half_] : g_tH[half_];

    int ct0 = blockIdx.x * 128;
    int bl  = blockIdx.y;
    int b = bl / LL, line = bl % LL;
    int t = threadIdx.x;
    int warp = t >> 5, lane = t & 31;
    int g = lane >> 2, tg = lane & 3;
    int mw = (warp >> 2) * 64;
    int nw = (warp & 3) * 24;

    const __half* Vp = Vb + (((size_t)(b * Cc + ct0)) * LL + line) * LL;
#pragma unroll
    for (int r = 0; r < 6; r++) {
        int idx = t + 256 * r;
        int c = idx / 12, j8 = (idx % 12) * 8;
        *(uint4*)&Vs[c * 104 + j8] = *(const uint4*)&Vp[(size_t)c * HW + j8];
    }
    const __half* Ap = Ab + (size_t)bl * LL * LL;
    for (int idx = t; idx < 96 * 12; idx += 256) {
        int i = idx / 12, j8 = (idx % 12) * 8;
        *(uint4*)&As2[i * 104 + j8] = *(const uint4*)&Ap[i * LL + j8];
    }
    __syncthreads();

    uint32_t vsB = smem_u32(Vs);
    uint32_t asB = smem_u32(As2);
    int aRow = (lane & 7) + ((lane >> 3) & 1) * 8;
    int aK8  = ((lane >> 4) & 1) * 8;
    int bRowN = lane & 7;
    int bK8  = ((lane >> 3) & 1) * 8;

    float acc[4][3][4];
#pragma unroll
    for (int i = 0; i < 4; i++)
#pragma unroll
        for (int j = 0; j < 3; j++)
#pragma unroll
            for (int r = 0; r < 4; r++) acc[i][j][r] = 0.f;

#pragma unroll
    for (int kk = 0; kk < 96; kk += 16) {
        uint32_t a[4][4], bb[3][2];
#pragma unroll
        for (int mt = 0; mt < 4; mt++) {
            uint32_t ad = vsB + (uint32_t)(((mw + mt * 16 + aRow) * 104 + kk + aK8) * 2);
            ldsm_x4(a[mt][0], a[mt][1], a[mt][2], a[mt][3], ad);
        }
#pragma unroll
        for (int nt = 0; nt < 3; nt++) {
            uint32_t bd = asB + (uint32_t)(((nw + nt * 8 + bRowN) * 104 + kk + bK8) * 2);
            ldsm_x2(bb[nt][0], bb[nt][1], bd);
        }
#pragma unroll
        for (int mt = 0; mt < 4; mt++)
#pragma unroll
            for (int nt = 0; nt < 3; nt++)
                mma_f16(acc[mt][nt][0], acc[mt][nt][1], acc[mt][nt][2], acc[mt][nt][3],
                        a[mt][0], a[mt][1], a[mt][2], a[mt][3],
                        bb[nt][0], bb[nt][1]);
    }

    __half* Op = Ob + ((size_t)bl * Cc + ct0) * LL;
#pragma unroll
    for (int mt = 0; mt < 4; mt++) {
        int m0g = mw + mt * 16 + g;
        __half* o0 = Op + (size_t)m0g * LL;
        __half* o1 = o0 + (size_t)8 * LL;
#pragma unroll
        for (int nt = 0; nt < 3; nt++) {
            int col = nw + nt * 8 + 2 * tg;
            *(__half2*)&o0[col] = __floats2half2_rn(acc[mt][nt][0], acc[mt][nt][1]);
            *(__half2*)&o1[col] = __floats2half2_rn(acc[mt][nt][2], acc[mt][nt][3]);
        }
    }
}

// ---------------- final: out = gamma*(tH^T + tW) + residual ------------------
__global__ void final_kernel(const float* __restrict__ x, const float* __restrict__ y,
                             const float* __restrict__ gamma, float* __restrict__ out)
{
    __shared__ __half2 til[32][17];
    int z  = blockIdx.z;
    int o  = z >> 12;           // B*C = 4096
    int bc = z & 4095;
    int b  = bc >> 9;
    int c  = bc & 511;
    int h0 = blockIdx.y * 32, w0 = blockIdx.x * 32;
    float g = gamma[0];
    const float* res = (o == 0 ? x : y) + (size_t)bc * HW;
    const __half* tH = g_tH[o];
    const __half* tW = g_tW[o];
    int tx = threadIdx.x, ty = threadIdx.y;   // 16 x 16

#pragma unroll
    for (int r = 0; r < 32; r += 16) {
        int w = ty + r;
        til[w][tx] = *(const __half2*)&tH[(((size_t)b * LL + (w0 + w)) * Cc + c) * LL + h0 + 2 * tx];
    }
    __syncthreads();
    float* op = out + (size_t)o * BCHW + (size_t)bc * HW;
#pragma unroll
    for (int r = 0; r < 32; r += 16) {
        int h = ty + r;
        int k = h >> 1, ln = h & 1;
        __half2 A = til[2 * tx][k];
        __half2 B = til[2 * tx + 1][k];
        float a = ln ? __high2float(A) : __low2float(A);
        float bq2 = ln ? __high2float(B) : __low2float(B);
        __half2 tw = *(const __half2*)&tW[(((size_t)b * LL + (h0 + h)) * Cc + c) * LL + w0 + 2 * tx];
        size_t ro = (size_t)(h0 + h) * LL + w0 + 2 * tx;
        float2 rs = *(const float2*)&res[ro];
        float2 ov;
        ov.x = g * (a   + __low2float(tw))  + rs.x;
        ov.y = g * (bq2 + __high2float(tw)) + rs.y;
        *(float2*)&op[ro] = ov;
    }
}

// ---------------------------------------------------------------------------
extern "C" void kernel_launch(void* const* d_in, const int* in_sizes, int n_in,
                              void* d_out, int out_size)
{
    const float* x     = (const float*)d_in[0];
    const float* y     = (const float*)d_in[1];
    const float* Wq    = (const float*)d_in[2];
    const float* bq    = (const float*)d_in[3];
    const float* Wk    = (const float*)d_in[4];
    const float* bk    = (const float*)d_in[5];
    const float* Wv    = (const float*)d_in[6];
    const float* bv    = (const float*)d_in[7];
    const float* gamma = (const float*)d_in[8];
    float* out = (float*)d_out;
    (void)in_sizes; (void)n_in; (void)out_size;

    __half *xh, *yh, *qk, *qkT, *v, *vT;
    cudaGetSymbolAddress((void**)&xh,  g_xh);
    cudaGetSymbolAddress((void**)&yh,  g_yh);
    cudaGetSymbolAddress((void**)&qk,  g_qk);
    cudaGetSymbolAddress((void**)&qkT, g_qkT);
    cudaGetSymbolAddress((void**)&v,   g_v);
    cudaGetSymbolAddress((void**)&vT,  g_vT);

    cudaFuncSetAttribute(proj_f16_kernel, cudaFuncAttributeMaxDynamicSharedMemorySize, PROJ_SMEM);

    // 0) convert inputs + stack weights to fp16
    f2h_kernel<<<dim3(BCHW / 2048, 2), 256>>>(x, y);
    weights_kernel<<<1280, 256>>>(Wq, bq, Wk, bk, Wv, bv);

    // 1) fused projections: single launch computes qk and v for both inputs
    proj_f16_kernel<<<dim3(72, 5, 16), 256, PROJ_SMEM>>>(xh, yh);

    // 2) transposes (contiguous [2] arrays -> single launch each)
    dim3 tb(16, 16);
    transpose16_kernel<<<dim3(3, 3, 2 * Bz * 128), tb>>>(qk, qkT);
    transpose16_kernel<<<dim3(3, 3, 2 * Bz * Cc),  tb>>>(v, vT);

    // 3) energies (4 variants in one launch)
    energy_kernel<<<dim3(Bz * LL, 4), 256>>>();

    // 4) joint softmax -> fp16 attention
    softmax_kernel<<<dim3(9216, 2), 256>>>();

    // 5) applies (4 variants in one launch)
    apply_f16_kernel<<<dim3(4, Bz * LL, 4), 256>>>();

    // 6) combine + residual
    final_kernel<<<dim3(3, 3, 2 * Bz * Cc), tb>>>(x, y, gamma, out);
}